// round 1
// baseline (speedup 1.0000x reference)
#include <cuda_runtime.h>
#include <cuda_bf16.h>

#define E_EDGES 160000
#define NNODES  10000
#define NELEM   90

// ---------------- scratch (device globals: allocation-free rule) ----------------
__device__ float g_h [E_EDGES * 128];   // h0 after layer0
__device__ float g_h2[E_EDGES * 128];   // h1 after layer1
__device__ float g_y [E_EDGES * 320];   // (h1@W2 + b2) * env * 0.2
__device__ int   g_hist [NNODES];
__device__ int   g_off  [NNODES + 1];
__device__ int   g_cur  [NNODES];
__device__ int   g_order[E_EDGES];

// ---------------- GEMM tiling constants ----------------
// layer0/layer1: BM=64, BN=128, BK=32, 256 threads, TM=8 x TN=4
#define AS_STRIDE 68     // pad: %32==4 -> conflict-free-ish, 16B-aligned rows

__device__ __forceinline__ float silu(float x) {
    return x / (1.0f + __expf(-x));
}

// ============================================================================
// Kernel 1: X = concat(dist, src_emb, tgt_emb) [E,384] @ W0 [384,128]
//           -> +b0 -> LN(g0,beta0) -> SiLU -> g_h
// ============================================================================
__global__ __launch_bounds__(256) void k_mlp0(
    const int*   __restrict__ an,
    const float* __restrict__ dist,
    const int*   __restrict__ ei,
    const float* __restrict__ semb,
    const float* __restrict__ temb,
    const float* __restrict__ W,
    const float* __restrict__ bias,
    const float* __restrict__ gamma,
    const float* __restrict__ betap)
{
    __shared__ __align__(16) float As[32 * AS_STRIDE];
    __shared__ __align__(16) float Bs[32 * 128];
    __shared__ int sSrc[64], sTgt[64];

    const int e0  = blockIdx.x * 64;
    const int tid = threadIdx.x;

    if (tid < 64) {
        int e = e0 + tid;
        sSrc[tid] = an[ei[e]] * 128;
        sTgt[tid] = an[ei[E_EDGES + e]] * 128;
    }
    __syncthreads();

    const int tx = tid & 31, ty = tid >> 5;
    const int rowBase = ty * 8, colBase = tx * 4;

    float acc[8][4];
#pragma unroll
    for (int i = 0; i < 8; i++)
#pragma unroll
        for (int j = 0; j < 4; j++) acc[i][j] = 0.0f;

    for (int k0 = 0; k0 < 384; k0 += 32) {
        const int seg  = k0 >> 7;
        const int koff = k0 & 127;
        // A tile: 64 edges x 32 k = 512 float4, 2 per thread
#pragma unroll
        for (int r = 0; r < 2; r++) {
            int v  = tid + r * 256;
            int el = v >> 3, kv = v & 7;
            const float* src;
            if (seg == 0)      src = dist + (size_t)(e0 + el) * 128 + koff;
            else if (seg == 1) src = semb + sSrc[el] + koff;
            else               src = temb + sTgt[el] + koff;
            float4 a = *(const float4*)(src + kv * 4);
            As[(kv * 4 + 0) * AS_STRIDE + el] = a.x;
            As[(kv * 4 + 1) * AS_STRIDE + el] = a.y;
            As[(kv * 4 + 2) * AS_STRIDE + el] = a.z;
            As[(kv * 4 + 3) * AS_STRIDE + el] = a.w;
        }
        // B tile: 32x128 = 1024 float4? no: 4096 floats = 1024 float4, 4/thread
#pragma unroll
        for (int r = 0; r < 4; r++) {
            int v = tid + r * 256;
            int kk = v >> 5, col4 = (v & 31) * 4;
            *(float4*)&Bs[kk * 128 + col4] =
                *(const float4*)(W + (size_t)(k0 + kk) * 128 + col4);
        }
        __syncthreads();
#pragma unroll
        for (int kk = 0; kk < 32; kk++) {
            float4 a0 = *(const float4*)&As[kk * AS_STRIDE + rowBase];
            float4 a1 = *(const float4*)&As[kk * AS_STRIDE + rowBase + 4];
            float4 b  = *(const float4*)&Bs[kk * 128 + colBase];
            float av[8] = {a0.x, a0.y, a0.z, a0.w, a1.x, a1.y, a1.z, a1.w};
            float bv[4] = {b.x, b.y, b.z, b.w};
#pragma unroll
            for (int i = 0; i < 8; i++)
#pragma unroll
                for (int j = 0; j < 4; j++) acc[i][j] += av[i] * bv[j];
        }
        __syncthreads();
    }

    // epilogue: +bias, LayerNorm over 128 (whole row lives in this warp), SiLU
    float4 bb = *(const float4*)(bias  + colBase);
    float4 gg = *(const float4*)(gamma + colBase);
    float4 be = *(const float4*)(betap + colBase);
    float g4[4] = {gg.x, gg.y, gg.z, gg.w};
    float e4[4] = {be.x, be.y, be.z, be.w};
    float b4[4] = {bb.x, bb.y, bb.z, bb.w};
#pragma unroll
    for (int i = 0; i < 8; i++) {
        float v[4];
#pragma unroll
        for (int j = 0; j < 4; j++) v[j] = acc[i][j] + b4[j];
        float s = v[0] + v[1] + v[2] + v[3];
        float q = v[0]*v[0] + v[1]*v[1] + v[2]*v[2] + v[3]*v[3];
#pragma unroll
        for (int o = 16; o > 0; o >>= 1) {
            s += __shfl_xor_sync(0xffffffffu, s, o);
            q += __shfl_xor_sync(0xffffffffu, q, o);
        }
        float mu   = s * (1.0f / 128.0f);
        float var  = q * (1.0f / 128.0f) - mu * mu;
        float rinv = rsqrtf(var + 1e-5f);
        float4 o4;
        float* po = &o4.x;
#pragma unroll
        for (int j = 0; j < 4; j++) {
            float x = (v[j] - mu) * rinv * g4[j] + e4[j];
            po[j] = silu(x);
        }
        *(float4*)(g_h + (size_t)(e0 + rowBase + i) * 128 + colBase) = o4;
    }
}

// ============================================================================
// Kernel 2: g_h [E,128] @ W1 [128,128] -> +b1 -> LN -> SiLU -> g_h2
// ============================================================================
__global__ __launch_bounds__(256) void k_mlp1(
    const float* __restrict__ W,
    const float* __restrict__ bias,
    const float* __restrict__ gamma,
    const float* __restrict__ betap)
{
    __shared__ __align__(16) float As[32 * AS_STRIDE];
    __shared__ __align__(16) float Bs[32 * 128];

    const int e0  = blockIdx.x * 64;
    const int tid = threadIdx.x;
    const int tx = tid & 31, ty = tid >> 5;
    const int rowBase = ty * 8, colBase = tx * 4;

    float acc[8][4];
#pragma unroll
    for (int i = 0; i < 8; i++)
#pragma unroll
        for (int j = 0; j < 4; j++) acc[i][j] = 0.0f;

    for (int k0 = 0; k0 < 128; k0 += 32) {
#pragma unroll
        for (int r = 0; r < 2; r++) {
            int v  = tid + r * 256;
            int el = v >> 3, kv = v & 7;
            float4 a = *(const float4*)(g_h + (size_t)(e0 + el) * 128 + k0 + kv * 4);
            As[(kv * 4 + 0) * AS_STRIDE + el] = a.x;
            As[(kv * 4 + 1) * AS_STRIDE + el] = a.y;
            As[(kv * 4 + 2) * AS_STRIDE + el] = a.z;
            As[(kv * 4 + 3) * AS_STRIDE + el] = a.w;
        }
#pragma unroll
        for (int r = 0; r < 4; r++) {
            int v = tid + r * 256;
            int kk = v >> 5, col4 = (v & 31) * 4;
            *(float4*)&Bs[kk * 128 + col4] =
                *(const float4*)(W + (size_t)(k0 + kk) * 128 + col4);
        }
        __syncthreads();
#pragma unroll
        for (int kk = 0; kk < 32; kk++) {
            float4 a0 = *(const float4*)&As[kk * AS_STRIDE + rowBase];
            float4 a1 = *(const float4*)&As[kk * AS_STRIDE + rowBase + 4];
            float4 b  = *(const float4*)&Bs[kk * 128 + colBase];
            float av[8] = {a0.x, a0.y, a0.z, a0.w, a1.x, a1.y, a1.z, a1.w};
            float bv[4] = {b.x, b.y, b.z, b.w};
#pragma unroll
            for (int i = 0; i < 8; i++)
#pragma unroll
                for (int j = 0; j < 4; j++) acc[i][j] += av[i] * bv[j];
        }
        __syncthreads();
    }

    float4 bb = *(const float4*)(bias  + colBase);
    float4 gg = *(const float4*)(gamma + colBase);
    float4 be = *(const float4*)(betap + colBase);
    float g4[4] = {gg.x, gg.y, gg.z, gg.w};
    float e4[4] = {be.x, be.y, be.z, be.w};
    float b4[4] = {bb.x, bb.y, bb.z, bb.w};
#pragma unroll
    for (int i = 0; i < 8; i++) {
        float v[4];
#pragma unroll
        for (int j = 0; j < 4; j++) v[j] = acc[i][j] + b4[j];
        float s = v[0] + v[1] + v[2] + v[3];
        float q = v[0]*v[0] + v[1]*v[1] + v[2]*v[2] + v[3]*v[3];
#pragma unroll
        for (int o = 16; o > 0; o >>= 1) {
            s += __shfl_xor_sync(0xffffffffu, s, o);
            q += __shfl_xor_sync(0xffffffffu, q, o);
        }
        float mu   = s * (1.0f / 128.0f);
        float var  = q * (1.0f / 128.0f) - mu * mu;
        float rinv = rsqrtf(var + 1e-5f);
        float4 o4;
        float* po = &o4.x;
#pragma unroll
        for (int j = 0; j < 4; j++) {
            float x = (v[j] - mu) * rinv * g4[j] + e4[j];
            po[j] = silu(x);
        }
        *(float4*)(g_h2 + (size_t)(e0 + rowBase + i) * 128 + colBase) = o4;
    }
}

// ============================================================================
// Kernel 3: g_h2 [E,128] @ W2 [128,320] -> +b2 -> *env*0.2 -> g_y
// BM=128, BN=64 (gridDim.y covers 320/64=5), BK=32, 256 threads, TM=8 x TN=4
// ============================================================================
#define AS2_STRIDE 132
__global__ __launch_bounds__(256) void k_gemm2(
    const float* __restrict__ W,
    const float* __restrict__ bias,
    const float* __restrict__ env)
{
    __shared__ __align__(16) float As[32 * AS2_STRIDE];
    __shared__ __align__(16) float Bs[32 * 64];
    __shared__ float sEnv[128];

    const int e0  = blockIdx.x * 128;
    const int n0  = blockIdx.y * 64;
    const int tid = threadIdx.x;

    if (tid < 128) sEnv[tid] = env[e0 + tid] * 0.2f;

    const int tx = tid & 15, ty = tid >> 4;
    const int rowBase = ty * 8, colBase = tx * 4;

    float acc[8][4];
#pragma unroll
    for (int i = 0; i < 8; i++)
#pragma unroll
        for (int j = 0; j < 4; j++) acc[i][j] = 0.0f;

    for (int k0 = 0; k0 < 128; k0 += 32) {
#pragma unroll
        for (int r = 0; r < 4; r++) {
            int v  = tid + r * 256;
            int el = v >> 3, kv = v & 7;
            float4 a = *(const float4*)(g_h2 + (size_t)(e0 + el) * 128 + k0 + kv * 4);
            As[(kv * 4 + 0) * AS2_STRIDE + el] = a.x;
            As[(kv * 4 + 1) * AS2_STRIDE + el] = a.y;
            As[(kv * 4 + 2) * AS2_STRIDE + el] = a.z;
            As[(kv * 4 + 3) * AS2_STRIDE + el] = a.w;
        }
#pragma unroll
        for (int r = 0; r < 2; r++) {
            int v = tid + r * 256;
            int kk = v >> 4, col4 = (v & 15) * 4;
            *(float4*)&Bs[kk * 64 + col4] =
                *(const float4*)(W + (size_t)(k0 + kk) * 320 + n0 + col4);
        }
        __syncthreads();
#pragma unroll
        for (int kk = 0; kk < 32; kk++) {
            float4 a0 = *(const float4*)&As[kk * AS2_STRIDE + rowBase];
            float4 a1 = *(const float4*)&As[kk * AS2_STRIDE + rowBase + 4];
            float4 b  = *(const float4*)&Bs[kk * 64 + colBase];
            float av[8] = {a0.x, a0.y, a0.z, a0.w, a1.x, a1.y, a1.z, a1.w};
            float bv[4] = {b.x, b.y, b.z, b.w};
#pragma unroll
            for (int i = 0; i < 8; i++)
#pragma unroll
                for (int j = 0; j < 4; j++) acc[i][j] += av[i] * bv[j];
        }
        __syncthreads();
    }

    float4 bb = *(const float4*)(bias + n0 + colBase);
    float b4[4] = {bb.x, bb.y, bb.z, bb.w};
#pragma unroll
    for (int i = 0; i < 8; i++) {
        float sc = sEnv[rowBase + i];
        float4 o4;
        o4.x = (acc[i][0] + b4[0]) * sc;
        o4.y = (acc[i][1] + b4[1]) * sc;
        o4.z = (acc[i][2] + b4[2]) * sc;
        o4.w = (acc[i][3] + b4[3]) * sc;
        *(float4*)(g_y + (size_t)(e0 + rowBase + i) * 320 + n0 + colBase) = o4;
    }
}

// ============================================================================
// Counting sort of edges by target node
// ============================================================================
__global__ void k_zero_hist() {
    int i = blockIdx.x * blockDim.x + threadIdx.x;
    if (i < NNODES) g_hist[i] = 0;
}

__global__ void k_hist(const int* __restrict__ ei) {
    int e = blockIdx.x * blockDim.x + threadIdx.x;
    if (e < E_EDGES) atomicAdd(&g_hist[ei[E_EDGES + e]], 1);
}

__global__ __launch_bounds__(1024) void k_scan() {
    __shared__ int part[1024];
    const int tid = threadIdx.x;
    const int base = tid * 10;
    int local[10];
    int s = 0;
#pragma unroll
    for (int j = 0; j < 10; j++) {
        int idx = base + j;
        int h = (idx < NNODES) ? g_hist[idx] : 0;
        local[j] = s;
        s += h;
    }
    part[tid] = s;
    __syncthreads();
    for (int o = 1; o < 1024; o <<= 1) {
        int v = 0;
        if (tid >= o) v = part[tid - o];
        __syncthreads();
        part[tid] += v;
        __syncthreads();
    }
    int prev = (tid == 0) ? 0 : part[tid - 1];
#pragma unroll
    for (int j = 0; j < 10; j++) {
        int idx = base + j;
        if (idx < NNODES) {
            g_off[idx] = prev + local[j];
            g_cur[idx] = prev + local[j];
        }
    }
    if (tid == 1023) g_off[NNODES] = prev + s;
}

__global__ void k_scatter(const int* __restrict__ ei) {
    int e = blockIdx.x * blockDim.x + threadIdx.x;
    if (e < E_EDGES) {
        int t = ei[E_EDGES + e];
        int p = atomicAdd(&g_cur[t], 1);
        g_order[p] = e;
    }
}

// ============================================================================
// Kernel 4: per-node wigner rotation + segment sum.
// out[n,m,c] = sum_{edges e->n} sum_l wig[e,m,l] * y[e,l,c]   (y already /5-scaled)
// One CTA per node, 4-edge batches for memory-level parallelism.
// ============================================================================
#define WB 4
__global__ __launch_bounds__(256) void k_wigner(
    const float* __restrict__ wig,
    float* __restrict__ out)
{
    const int node = blockIdx.x;
    const int tid  = threadIdx.x;
    __shared__ __align__(16) float acc[1600];
    __shared__ __align__(16) float ys[WB * 320];
    __shared__ float sw[WB * 128];

    for (int i = tid; i < 1600; i += 256) acc[i] = 0.0f;

    const int beg = g_off[node];
    const int end = g_off[node + 1];

    for (int p = beg; p < end; p += WB) {
        const int nb = min(WB, end - p);
        __syncthreads();
        for (int j = 0; j < nb; j++) {
            int e = g_order[p + j];
            if (tid < 80)
                *(float4*)&ys[j * 320 + tid * 4] =
                    *(const float4*)(g_y + (size_t)e * 320 + tid * 4);
            if (tid >= 128 && tid < 253) {
                int q = tid - 128;
                int m = q / 5, l = q - m * 5;
                sw[j * 128 + q] = wig[(size_t)e * 625 + m * 25 + l];
            }
        }
        __syncthreads();
        for (int i = tid; i < 1600; i += 256) {
            int m = i >> 6, c = i & 63;
            float s = acc[i];
            for (int j = 0; j < nb; j++) {
                const float* w  = &sw[j * 128 + m * 5];
                const float* yy = &ys[j * 320];
                s += w[0] * yy[c]       + w[1] * yy[64 + c] + w[2] * yy[128 + c]
                   + w[3] * yy[192 + c] + w[4] * yy[256 + c];
            }
            acc[i] = s;
        }
    }
    __syncthreads();
    for (int i = tid; i < 1600; i += 256)
        out[(size_t)node * 1600 + i] = acc[i];
}

// ============================================================================
extern "C" void kernel_launch(void* const* d_in, const int* in_sizes, int n_in,
                              void* d_out, int out_size)
{
    const int*   an   = (const int*)  d_in[0];   // atomic_numbers [N]
    const float* dist = (const float*)d_in[1];   // edge_distance [E,128]
    const int*   ei   = (const int*)  d_in[2];   // edge_index [2,E]
    const float* env  = (const float*)d_in[3];   // edge_envelope_weight [E,1]
    const float* semb = (const float*)d_in[4];   // source_emb [90,128]
    const float* temb = (const float*)d_in[5];   // target_emb [90,128]
    const float* w0   = (const float*)d_in[6];
    const float* b0   = (const float*)d_in[7];
    const float* g0   = (const float*)d_in[8];
    const float* be0  = (const float*)d_in[9];
    const float* w1   = (const float*)d_in[10];
    const float* b1   = (const float*)d_in[11];
    const float* g1   = (const float*)d_in[12];
    const float* be1  = (const float*)d_in[13];
    const float* w2   = (const float*)d_in[14];
    const float* b2   = (const float*)d_in[15];
    const float* wig  = (const float*)d_in[16];
    float* out = (float*)d_out;

    k_mlp0 <<<E_EDGES / 64, 256>>>(an, dist, ei, semb, temb, w0, b0, g0, be0);
    k_mlp1 <<<E_EDGES / 64, 256>>>(w1, b1, g1, be1);
    k_gemm2<<<dim3(E_EDGES / 128, 5), 256>>>(w2, b2, env);

    k_zero_hist<<<(NNODES + 255) / 256, 256>>>();
    k_hist     <<<E_EDGES / 256, 256>>>(ei);
    k_scan     <<<1, 1024>>>();
    k_scatter  <<<E_EDGES / 256, 256>>>(ei);

    k_wigner<<<NNODES, 256>>>(wig, out);
}

// round 3
// speedup vs baseline: 1.3986x; 1.3986x over previous
#include <cuda_runtime.h>
#include <cuda_bf16.h>
#include <cstdint>

#define E_EDGES 160000
#define NNODES  10000

// ---------------- scratch (device globals) ----------------
__device__ __align__(16) __nv_bfloat16 g_h_hi [E_EDGES * 128];
__device__ __align__(16) __nv_bfloat16 g_h_lo [E_EDGES * 128];
__device__ __align__(16) __nv_bfloat16 g_h2_hi[E_EDGES * 128];
__device__ __align__(16) __nv_bfloat16 g_h2_lo[E_EDGES * 128];
__device__ __align__(16) float g_y [E_EDGES * 320];
// transposed split weights Wt[n][k]
__device__ __align__(16) __nv_bfloat16 W0t_hi[128 * 128];   // dist part only
__device__ __align__(16) __nv_bfloat16 W0t_lo[128 * 128];
__device__ __align__(16) __nv_bfloat16 W1t_hi[128 * 128];
__device__ __align__(16) __nv_bfloat16 W1t_lo[128 * 128];
__device__ __align__(16) __nv_bfloat16 W2t_hi[320 * 128];
__device__ __align__(16) __nv_bfloat16 W2t_lo[320 * 128];
// precomputed embedding projections (fp32 exact)
__device__ __align__(16) float g_Psrc[90 * 128];
__device__ __align__(16) float g_Ptgt[90 * 128];
__device__ int g_hist [NNODES];
__device__ int g_off  [NNODES + 1];
__device__ int g_cur  [NNODES];
__device__ int g_order[E_EDGES];

// ---------------- helpers ----------------
__device__ __forceinline__ uint32_t smem_u32(const void* p) {
    uint32_t a;
    asm("{ .reg .u64 t; cvta.to.shared.u64 t, %1; cvt.u32.u64 %0, t; }" : "=r"(a) : "l"(p));
    return a;
}
__device__ __forceinline__ void ldm4(uint32_t* r, uint32_t addr) {
    asm volatile("ldmatrix.sync.aligned.m8n8.x4.shared.b16 {%0,%1,%2,%3}, [%4];"
                 : "=r"(r[0]), "=r"(r[1]), "=r"(r[2]), "=r"(r[3]) : "r"(addr));
}
__device__ __forceinline__ void ldm2(uint32_t* r, uint32_t addr) {
    asm volatile("ldmatrix.sync.aligned.m8n8.x2.shared.b16 {%0,%1}, [%2];"
                 : "=r"(r[0]), "=r"(r[1]) : "r"(addr));
}
__device__ __forceinline__ void mma_bf16(float* c, const uint32_t* a, const uint32_t* b) {
    asm volatile(
        "mma.sync.aligned.m16n8k16.row.col.f32.bf16.bf16.f32 "
        "{%0,%1,%2,%3}, {%4,%5,%6,%7}, {%8,%9}, {%0,%1,%2,%3};"
        : "+f"(c[0]), "+f"(c[1]), "+f"(c[2]), "+f"(c[3])
        : "r"(a[0]), "r"(a[1]), "r"(a[2]), "r"(a[3]), "r"(b[0]), "r"(b[1]));
}
__device__ __forceinline__ float silu(float x) { return x / (1.0f + __expf(-x)); }
__device__ __forceinline__ unsigned short bf_bits(__nv_bfloat16 h) {
    return *reinterpret_cast<unsigned short*>(&h);
}
__device__ __forceinline__ void split8(const float* f, uint4& hq, uint4& lq) {
    __nv_bfloat16* hp = (__nv_bfloat16*)&hq;
    __nv_bfloat16* lp = (__nv_bfloat16*)&lq;
#pragma unroll
    for (int j = 0; j < 8; j++) {
        __nv_bfloat16 h = __float2bfloat16(f[j]);
        hp[j] = h;
        lp[j] = __float2bfloat16(f[j] - __bfloat162float(h));
    }
}

// row stride inside A/B smem tiles: 72 bf16 = 144 bytes (conflict-free ldmatrix)
#define RS 144

// ============================================================================
// k_prep: transpose+split weights. W0 dist rows only (k<128).
// ============================================================================
__global__ void k_prep(const float* __restrict__ w0, const float* __restrict__ w1,
                       const float* __restrict__ w2)
{
    int i = blockIdx.x * blockDim.x + threadIdx.x;
    const int S0 = 128 * 128, S1 = 128 * 128, S2 = 320 * 128;
    if (i < S0) {
        int n = i >> 7, k = i & 127;
        float x = w0[(size_t)k * 128 + n];
        __nv_bfloat16 h = __float2bfloat16(x);
        W0t_hi[i] = h; W0t_lo[i] = __float2bfloat16(x - __bfloat162float(h));
    } else if (i < S0 + S1) {
        int j = i - S0; int n = j >> 7, k = j & 127;
        float x = w1[(size_t)k * 128 + n];
        __nv_bfloat16 h = __float2bfloat16(x);
        W1t_hi[j] = h; W1t_lo[j] = __float2bfloat16(x - __bfloat162float(h));
    } else if (i < S0 + S1 + S2) {
        int j = i - S0 - S1; int n = j >> 7, k = j & 127;
        float x = w2[(size_t)k * 320 + n];
        __nv_bfloat16 h = __float2bfloat16(x);
        W2t_hi[j] = h; W2t_lo[j] = __float2bfloat16(x - __bfloat162float(h));
    }
}

// ============================================================================
// k_pemb: P_src[z][n] = sum_k semb[z][k] * w0[128+k][n]  (fp32, 180 blocks)
// ============================================================================
__global__ __launch_bounds__(128) void k_pemb(
    const float* __restrict__ semb, const float* __restrict__ temb,
    const float* __restrict__ w0)
{
    __shared__ float er[128];
    const int bx = blockIdx.x;
    const int z = (bx < 90) ? bx : bx - 90;
    const int tid = threadIdx.x;
    const float* emb = (bx < 90) ? semb : temb;
    const int off = (bx < 90) ? 128 : 256;
    er[tid] = emb[z * 128 + tid];
    __syncthreads();
    float s = 0.f;
#pragma unroll 8
    for (int k = 0; k < 128; k++)
        s += er[k] * w0[(size_t)(off + k) * 128 + tid];
    float* P = (bx < 90) ? g_Psrc : g_Ptgt;
    P[z * 128 + tid] = s;
}

// ============================================================================
// k_mlp: HMMA GEMM [128 x 128] x [128 x 128] (bf16x3) + bias (+P gathers for
// layer0) + LN + SiLU -> bf16 hi/lo activations.
// 512 threads, 16 warps in 4x4; warp tile 32x32.
// ============================================================================
#define SA_HI 0
#define SA_LO 18432
#define SB_HI 36864
#define SB_LO 55296
#define RED_S 73728
#define RED_Q 75776
#define SBIAS 77824
#define SGAM  78336
#define SBET  78848
#define SZS   79360
#define SZT   79872
#define G_SIZE 80384
#define STGLO_W (36864 / 4)

__global__ __launch_bounds__(512) void k_mlp(
    int layer,
    const int* __restrict__ an, const float* __restrict__ dist,
    const int* __restrict__ ei,
    const float* __restrict__ bias, const float* __restrict__ gamma,
    const float* __restrict__ betap)
{
    extern __shared__ __align__(16) unsigned char sm[];
    const uint32_t sb = smem_u32(sm);
    const int tid = threadIdx.x;
    const int wid = tid >> 5, lane = tid & 31;
    const int gid = lane >> 2, qid = lane & 3;
    const int wid_m = wid >> 2, wid_n = wid & 3;
    const int warpRow = wid_m * 32, warpCol = wid_n * 32;
    const int e0 = blockIdx.x * 128;

    if (tid < 128) {
        ((float*)(sm + SBIAS))[tid] = bias[tid];
        ((float*)(sm + SGAM))[tid]  = gamma[tid];
        ((float*)(sm + SBET))[tid]  = betap[tid];
        if (layer == 0) {
            ((int*)(sm + SZS))[tid] = an[ei[e0 + tid]];
            ((int*)(sm + SZT))[tid] = an[ei[E_EDGES + e0 + tid]];
        }
    }

    float acc[2][4][4];
#pragma unroll
    for (int i = 0; i < 2; i++)
#pragma unroll
        for (int j = 0; j < 4; j++)
#pragma unroll
            for (int c = 0; c < 4; c++) acc[i][j][c] = 0.f;

    const __nv_bfloat16* Bhi = layer ? W1t_hi : W0t_hi;
    const __nv_bfloat16* Blo = layer ? W1t_lo : W0t_lo;

    for (int kc = 0; kc < 2; kc++) {
        __syncthreads();
        // ---- A tile ----
        if (layer == 0) {
            int row = tid >> 2, cg2 = tid & 3;
            const float* sp = dist + (size_t)(e0 + row) * 128 + kc * 64 + cg2 * 16;
            float f[16];
#pragma unroll
            for (int q = 0; q < 4; q++) {
                float4 x = ((const float4*)sp)[q];
                f[q * 4] = x.x; f[q * 4 + 1] = x.y; f[q * 4 + 2] = x.z; f[q * 4 + 3] = x.w;
            }
            uint4 h0, l0, h1, l1;
            split8(f, h0, l0); split8(f + 8, h1, l1);
            uint32_t off = row * RS + cg2 * 32;
            *(uint4*)(sm + SA_HI + off)      = h0;
            *(uint4*)(sm + SA_HI + off + 16) = h1;
            *(uint4*)(sm + SA_LO + off)      = l0;
            *(uint4*)(sm + SA_LO + off + 16) = l1;
        } else {
#pragma unroll
            for (int r = 0; r < 2; r++) {
                int u = tid + r * 512;
                int row = u >> 3, cg = u & 7;
                size_t gi = (size_t)(e0 + row) * 16 + kc * 8 + cg;
                uint32_t off = row * RS + cg * 16;
                *(uint4*)(sm + SA_HI + off) = ((const uint4*)g_h_hi)[gi];
                *(uint4*)(sm + SA_LO + off) = ((const uint4*)g_h_lo)[gi];
            }
        }
        // ---- B tile (weights Wt[n][k]) ----
#pragma unroll
        for (int r = 0; r < 2; r++) {
            int u = tid + r * 512;
            int n = u >> 3, cg = u & 7;
            size_t gi = (size_t)n * 16 + kc * 8 + cg;
            uint32_t off = n * RS + cg * 16;
            *(uint4*)(sm + SB_HI + off) = ((const uint4*)Bhi)[gi];
            *(uint4*)(sm + SB_LO + off) = ((const uint4*)Blo)[gi];
        }
        __syncthreads();

#pragma unroll
        for (int ks = 0; ks < 4; ks++) {
            const int kk = ks * 16;
            // A addresses: rows 0..15 of frag, both k-halves
            const int rA = ((lane >> 3) & 1) * 8 + (lane & 7);
            const int cA = kk + (lane >> 4) * 8;
            uint32_t a_hi[2][4], a_lo[2][4];
#pragma unroll
            for (int i = 0; i < 2; i++) {
                uint32_t ad = sb + (warpRow + i * 16 + rA) * RS + cA * 2;
                ldm4(a_hi[i], ad + SA_HI);
                ldm4(a_lo[i], ad + SA_LO);
            }
            // B: two ldm4 cover 32 n-rows
            uint32_t b_hi[4][2], b_lo[4][2];
#pragma unroll
            for (int t = 0; t < 2; t++) {
                const int nB = warpCol + t * 16 + ((lane >> 3) & 1) * 8 + (lane & 7);
                const int cB = kk + (lane >> 4) * 8;
                uint32_t bd = sb + nB * RS + cB * 2;
                uint32_t r4[4];
                ldm4(r4, bd + SB_HI);
                b_hi[t * 2][0] = r4[0]; b_hi[t * 2 + 1][0] = r4[1];
                b_hi[t * 2][1] = r4[2]; b_hi[t * 2 + 1][1] = r4[3];
                ldm4(r4, bd + SB_LO);
                b_lo[t * 2][0] = r4[0]; b_lo[t * 2 + 1][0] = r4[1];
                b_lo[t * 2][1] = r4[2]; b_lo[t * 2 + 1][1] = r4[3];
            }
#pragma unroll
            for (int i = 0; i < 2; i++)
#pragma unroll
                for (int j = 0; j < 4; j++) {
                    mma_bf16(acc[i][j], a_hi[i], b_hi[j]);
                    mma_bf16(acc[i][j], a_hi[i], b_lo[j]);
                    mma_bf16(acc[i][j], a_lo[i], b_hi[j]);
                }
        }
    }
    __syncthreads();

    // ---- epilogue: +bias (+P), LN, SiLU, split-store ----
    const float* bs = (const float*)(sm + SBIAS);
    const int* zsA = (const int*)(sm + SZS);
    const int* ztA = (const int*)(sm + SZT);

#pragma unroll
    for (int i = 0; i < 2; i++)
#pragma unroll
        for (int h = 0; h < 2; h++) {
            int row = warpRow + i * 16 + h * 8 + gid;
            const float* ps = layer ? nullptr : (g_Psrc + (size_t)zsA[row] * 128);
            const float* pt = layer ? nullptr : (g_Ptgt + (size_t)ztA[row] * 128);
            float s = 0.f, q = 0.f;
#pragma unroll
            for (int j = 0; j < 4; j++) {
                int col = warpCol + j * 8 + qid * 2;
                float v0 = acc[i][j][2 * h]     + bs[col];
                float v1 = acc[i][j][2 * h + 1] + bs[col + 1];
                if (layer == 0) {
                    float2 a = *(const float2*)(ps + col);
                    float2 b = *(const float2*)(pt + col);
                    v0 += a.x + b.x; v1 += a.y + b.y;
                }
                acc[i][j][2 * h] = v0; acc[i][j][2 * h + 1] = v1;
                s += v0 + v1; q += v0 * v0 + v1 * v1;
            }
            s += __shfl_xor_sync(0xffffffffu, s, 1);
            s += __shfl_xor_sync(0xffffffffu, s, 2);
            q += __shfl_xor_sync(0xffffffffu, q, 1);
            q += __shfl_xor_sync(0xffffffffu, q, 2);
            if (qid == 0) {
                ((float*)(sm + RED_S))[row * 4 + wid_n] = s;
                ((float*)(sm + RED_Q))[row * 4 + wid_n] = q;
            }
        }
    __syncthreads();

    const float* gs  = (const float*)(sm + SGAM);
    const float* bes = (const float*)(sm + SBET);
    uint32_t* stg = (uint32_t*)sm;
#pragma unroll
    for (int i = 0; i < 2; i++)
#pragma unroll
        for (int h = 0; h < 2; h++) {
            int row = warpRow + i * 16 + h * 8 + gid;
            const float* rS = (const float*)(sm + RED_S) + row * 4;
            const float* rQ = (const float*)(sm + RED_Q) + row * 4;
            float st = rS[0] + rS[1] + rS[2] + rS[3];
            float qt = rQ[0] + rQ[1] + rQ[2] + rQ[3];
            float mu   = st * (1.0f / 128.0f);
            float var  = qt * (1.0f / 128.0f) - mu * mu;
            float rinv = rsqrtf(var + 1e-5f);
#pragma unroll
            for (int j = 0; j < 4; j++) {
                int col = warpCol + j * 8 + qid * 2;
                float y0 = silu((acc[i][j][2 * h]     - mu) * rinv * gs[col]     + bes[col]);
                float y1 = silu((acc[i][j][2 * h + 1] - mu) * rinv * gs[col + 1] + bes[col + 1]);
                __nv_bfloat16 h0 = __float2bfloat16(y0), h1 = __float2bfloat16(y1);
                __nv_bfloat16 l0 = __float2bfloat16(y0 - __bfloat162float(h0));
                __nv_bfloat16 l1 = __float2bfloat16(y1 - __bfloat162float(h1));
                int si = row * 65 + (warpCol >> 1) + j * 4 + qid;
                stg[si]           = (uint32_t)bf_bits(h0) | ((uint32_t)bf_bits(h1) << 16);
                stg[STGLO_W + si] = (uint32_t)bf_bits(l0) | ((uint32_t)bf_bits(l1) << 16);
            }
        }
    __syncthreads();
    uint32_t* oh = (uint32_t*)(layer ? g_h2_hi : g_h_hi);
    uint32_t* ol = (uint32_t*)(layer ? g_h2_lo : g_h_lo);
#pragma unroll
    for (int r = 0; r < 16; r++) {
        int idx = tid + r * 512;
        int rr = idx >> 6, w = idx & 63;
        size_t go = (size_t)(e0 + rr) * 64 + w;
        oh[go] = stg[rr * 65 + w];
        ol[go] = stg[STGLO_W + rr * 65 + w];
    }
}

// ============================================================================
// k_out: [128 x 128] x [128 x 160] HMMA bf16x3, +b2, *env*0.2 -> g_y
// grid (1250, 2); 512 threads; warp tile 32x40.
// ============================================================================
#define H_AHI 0
#define H_ALO 18432
#define H_BHI 36864
#define H_BLO 59904
#define H_BIAS 82944
#define H_ENV 83584
#define H_SIZE 84096

__global__ __launch_bounds__(512) void k_out(
    const float* __restrict__ bias, const float* __restrict__ env)
{
    extern __shared__ __align__(16) unsigned char sm[];
    const uint32_t sb = smem_u32(sm);
    const int tid = threadIdx.x;
    const int wid = tid >> 5, lane = tid & 31;
    const int gid = lane >> 2, qid = lane & 3;
    const int wid_m = wid >> 2, wid_n = wid & 3;
    const int warpRow = wid_m * 32, warpCol = wid_n * 40;
    const int e0 = blockIdx.x * 128;
    const int n0 = blockIdx.y * 160;

    if (tid < 160) ((float*)(sm + H_BIAS))[tid] = bias[n0 + tid];
    if (tid < 128) ((float*)(sm + H_ENV))[tid] = env[e0 + tid] * 0.2f;

    float acc[2][5][4];
#pragma unroll
    for (int i = 0; i < 2; i++)
#pragma unroll
        for (int j = 0; j < 5; j++)
#pragma unroll
            for (int c = 0; c < 4; c++) acc[i][j][c] = 0.f;

    for (int kc = 0; kc < 2; kc++) {
        __syncthreads();
#pragma unroll
        for (int r = 0; r < 2; r++) {
            int u = tid + r * 512;
            int row = u >> 3, cg = u & 7;
            size_t gi = (size_t)(e0 + row) * 16 + kc * 8 + cg;
            uint32_t off = row * RS + cg * 16;
            *(uint4*)(sm + H_AHI + off) = ((const uint4*)g_h2_hi)[gi];
            *(uint4*)(sm + H_ALO + off) = ((const uint4*)g_h2_lo)[gi];
        }
        for (int u = tid; u < 1280; u += 512) {
            int n = u >> 3, cg = u & 7;
            size_t gi = (size_t)(n0 + n) * 16 + kc * 8 + cg;
            uint32_t off = n * RS + cg * 16;
            *(uint4*)(sm + H_BHI + off) = ((const uint4*)W2t_hi)[gi];
            *(uint4*)(sm + H_BLO + off) = ((const uint4*)W2t_lo)[gi];
        }
        __syncthreads();

#pragma unroll
        for (int ks = 0; ks < 4; ks++) {
            const int kk = ks * 16;
            const int rA = ((lane >> 3) & 1) * 8 + (lane & 7);
            const int cA = kk + (lane >> 4) * 8;
            uint32_t a_hi[2][4], a_lo[2][4];
#pragma unroll
            for (int i = 0; i < 2; i++) {
                uint32_t ad = sb + (warpRow + i * 16 + rA) * RS + cA * 2;
                ldm4(a_hi[i], ad + H_AHI);
                ldm4(a_lo[i], ad + H_ALO);
            }
            uint32_t b_hi[5][2], b_lo[5][2];
#pragma unroll
            for (int t = 0; t < 2; t++) {
                const int nB = warpCol + t * 16 + ((lane >> 3) & 1) * 8 + (lane & 7);
                const int cB = kk + (lane >> 4) * 8;
                uint32_t bd = sb + nB * RS + cB * 2;
                uint32_t r4[4];
                ldm4(r4, bd + H_BHI);
                b_hi[t * 2][0] = r4[0]; b_hi[t * 2 + 1][0] = r4[1];
                b_hi[t * 2][1] = r4[2]; b_hi[t * 2 + 1][1] = r4[3];
                ldm4(r4, bd + H_BLO);
                b_lo[t * 2][0] = r4[0]; b_lo[t * 2 + 1][0] = r4[1];
                b_lo[t * 2][1] = r4[2]; b_lo[t * 2 + 1][1] = r4[3];
            }
            {   // fifth n-frag via ldm2 (lanes 0-15 supply addresses)
                const int nB = warpCol + 32 + (lane & 7);
                const int cB = kk + ((lane >> 3) & 1) * 8;
                uint32_t bd = sb + nB * RS + cB * 2;
                ldm2(b_hi[4], bd + H_BHI);
                ldm2(b_lo[4], bd + H_BLO);
            }
#pragma unroll
            for (int i = 0; i < 2; i++)
#pragma unroll
                for (int j = 0; j < 5; j++) {
                    mma_bf16(acc[i][j], a_hi[i], b_hi[j]);
                    mma_bf16(acc[i][j], a_hi[i], b_lo[j]);
                    mma_bf16(acc[i][j], a_lo[i], b_hi[j]);
                }
        }
    }

    const float* bsp = (const float*)(sm + H_BIAS);
    const float* ep  = (const float*)(sm + H_ENV);
#pragma unroll
    for (int i = 0; i < 2; i++)
#pragma unroll
        for (int h = 0; h < 2; h++) {
            int row = warpRow + i * 16 + h * 8 + gid;
            float es = ep[row];
            float* yp = g_y + (size_t)(e0 + row) * 320 + n0;
#pragma unroll
            for (int j = 0; j < 5; j++) {
                int col = warpCol + j * 8 + qid * 2;
                float2 o;
                o.x = (acc[i][j][2 * h]     + bsp[col])     * es;
                o.y = (acc[i][j][2 * h + 1] + bsp[col + 1]) * es;
                *(float2*)(yp + col) = o;
            }
        }
}

// ============================================================================
// counting sort by target node
// ============================================================================
__global__ void k_zero_hist() {
    int i = blockIdx.x * blockDim.x + threadIdx.x;
    if (i < NNODES) g_hist[i] = 0;
}
__global__ void k_hist(const int* __restrict__ ei) {
    int e = blockIdx.x * blockDim.x + threadIdx.x;
    if (e < E_EDGES) atomicAdd(&g_hist[ei[E_EDGES + e]], 1);
}
__global__ __launch_bounds__(1024) void k_scan() {
    __shared__ int part[1024];
    const int tid = threadIdx.x;
    const int base = tid * 10;
    int local[10];
    int s = 0;
#pragma unroll
    for (int j = 0; j < 10; j++) {
        int idx = base + j;
        int h = (idx < NNODES) ? g_hist[idx] : 0;
        local[j] = s; s += h;
    }
    part[tid] = s;
    __syncthreads();
    for (int o = 1; o < 1024; o <<= 1) {
        int v = 0;
        if (tid >= o) v = part[tid - o];
        __syncthreads();
        part[tid] += v;
        __syncthreads();
    }
    int prev = (tid == 0) ? 0 : part[tid - 1];
#pragma unroll
    for (int j = 0; j < 10; j++) {
        int idx = base + j;
        if (idx < NNODES) { g_off[idx] = prev + local[j]; g_cur[idx] = prev + local[j]; }
    }
    if (tid == 1023) g_off[NNODES] = prev + s;
}
__global__ void k_scatter(const int* __restrict__ ei) {
    int e = blockIdx.x * blockDim.x + threadIdx.x;
    if (e < E_EDGES) {
        int t = ei[E_EDGES + e];
        int p = atomicAdd(&g_cur[t], 1);
        g_order[p] = e;
    }
}

// ============================================================================
// k_wigner: per-node rotate + segment sum
// ============================================================================
#define WB 4
__global__ __launch_bounds__(256) void k_wigner(
    const float* __restrict__ wig, float* __restrict__ out)
{
    const int node = blockIdx.x;
    const int tid  = threadIdx.x;
    __shared__ __align__(16) float acc[1600];
    __shared__ __align__(16) float ys[WB * 320];
    __shared__ float sw[WB * 128];

    for (int i = tid; i < 1600; i += 256) acc[i] = 0.0f;
    const int beg = g_off[node];
    const int end = g_off[node + 1];

    for (int p = beg; p < end; p += WB) {
        const int nb = min(WB, end - p);
        __syncthreads();
        for (int j = 0; j < nb; j++) {
            int e = g_order[p + j];
            if (tid < 80)
                *(float4*)&ys[j * 320 + tid * 4] =
                    *(const float4*)(g_y + (size_t)e * 320 + tid * 4);
            if (tid >= 128 && tid < 253) {
                int qi = tid - 128;
                int m = qi / 5, l = qi - m * 5;
                sw[j * 128 + qi] = wig[(size_t)e * 625 + m * 25 + l];
            }
        }
        __syncthreads();
        for (int i = tid; i < 1600; i += 256) {
            int m = i >> 6, c = i & 63;
            float s = acc[i];
            for (int j = 0; j < nb; j++) {
                const float* w  = &sw[j * 128 + m * 5];
                const float* yy = &ys[j * 320];
                s += w[0] * yy[c]       + w[1] * yy[64 + c] + w[2] * yy[128 + c]
                   + w[3] * yy[192 + c] + w[4] * yy[256 + c];
            }
            acc[i] = s;
        }
    }
    __syncthreads();
    for (int i = tid; i < 1600; i += 256)
        out[(size_t)node * 1600 + i] = acc[i];
}

// ============================================================================
extern "C" void kernel_launch(void* const* d_in, const int* in_sizes, int n_in,
                              void* d_out, int out_size)
{
    const int*   an   = (const int*)  d_in[0];
    const float* dist = (const float*)d_in[1];
    const int*   ei   = (const int*)  d_in[2];
    const float* env  = (const float*)d_in[3];
    const float* semb = (const float*)d_in[4];
    const float* temb = (const float*)d_in[5];
    const float* w0   = (const float*)d_in[6];
    const float* b0   = (const float*)d_in[7];
    const float* g0   = (const float*)d_in[8];
    const float* be0  = (const float*)d_in[9];
    const float* w1   = (const float*)d_in[10];
    const float* b1   = (const float*)d_in[11];
    const float* g1   = (const float*)d_in[12];
    const float* be1  = (const float*)d_in[13];
    const float* w2   = (const float*)d_in[14];
    const float* b2   = (const float*)d_in[15];
    const float* wig  = (const float*)d_in[16];
    float* out = (float*)d_out;

    cudaFuncSetAttribute(k_mlp, cudaFuncAttributeMaxDynamicSharedMemorySize, G_SIZE);
    cudaFuncSetAttribute(k_out, cudaFuncAttributeMaxDynamicSharedMemorySize, H_SIZE);

    // order chosen so ncu (-s 5 -c 1) profiles k_mlp layer 0
    k_prep     <<<(128 * 128 * 2 + 320 * 128 + 255) / 256, 256>>>(w0, w1, w2);
    k_pemb     <<<180, 128>>>(semb, temb, w0);
    k_zero_hist<<<(NNODES + 255) / 256, 256>>>();
    k_hist     <<<E_EDGES / 256, 256>>>(ei);
    k_scan     <<<1, 1024>>>();

    k_mlp<<<E_EDGES / 128, 512, G_SIZE>>>(0, an, dist, ei, b0, g0, be0);
    k_mlp<<<E_EDGES / 128, 512, G_SIZE>>>(1, an, dist, ei, b1, g1, be1);
    k_out<<<dim3(E_EDGES / 128, 2), 512, H_SIZE>>>(b2, env);

    k_scatter  <<<E_EDGES / 256, 256>>>(ei);
    k_wigner<<<NNODES, 256>>>(wig, out);
}

// round 4
// speedup vs baseline: 1.6560x; 1.1840x over previous
#include <cuda_runtime.h>
#include <cuda_bf16.h>
#include <cstdint>

#define E_EDGES 160000
#define NNODES  10000

// ---------------- scratch (device globals) ----------------
__device__ __align__(16) __nv_bfloat16 g_h_hi [E_EDGES * 128];
__device__ __align__(16) __nv_bfloat16 g_h_lo [E_EDGES * 128];
__device__ __align__(16) __nv_bfloat16 g_h2_hi[E_EDGES * 128];
__device__ __align__(16) __nv_bfloat16 g_h2_lo[E_EDGES * 128];
__device__ __align__(16) float g_y [E_EDGES * 320];
// transposed split weights Wt[n][k]
__device__ __align__(16) __nv_bfloat16 W0t_hi[128 * 128];   // dist part only
__device__ __align__(16) __nv_bfloat16 W0t_lo[128 * 128];
__device__ __align__(16) __nv_bfloat16 W1t_hi[128 * 128];
__device__ __align__(16) __nv_bfloat16 W1t_lo[128 * 128];
__device__ __align__(16) __nv_bfloat16 W2t_hi[320 * 128];
__device__ __align__(16) __nv_bfloat16 W2t_lo[320 * 128];
// precomputed embedding projections (fp32 exact)
__device__ __align__(16) float g_Psrc[90 * 128];
__device__ __align__(16) float g_Ptgt[90 * 128];
__device__ int g_hist [NNODES];
__device__ int g_off  [NNODES + 1];
__device__ int g_cur  [NNODES];
__device__ int g_order[E_EDGES];

// ---------------- helpers ----------------
__device__ __forceinline__ uint32_t smem_u32(const void* p) {
    uint32_t a;
    asm("{ .reg .u64 t; cvta.to.shared.u64 t, %1; cvt.u32.u64 %0, t; }" : "=r"(a) : "l"(p));
    return a;
}
__device__ __forceinline__ void ldm4(uint32_t* r, uint32_t addr) {
    asm volatile("ldmatrix.sync.aligned.m8n8.x4.shared.b16 {%0,%1,%2,%3}, [%4];"
                 : "=r"(r[0]), "=r"(r[1]), "=r"(r[2]), "=r"(r[3]) : "r"(addr));
}
__device__ __forceinline__ void ldm2(uint32_t* r, uint32_t addr) {
    asm volatile("ldmatrix.sync.aligned.m8n8.x2.shared.b16 {%0,%1}, [%2];"
                 : "=r"(r[0]), "=r"(r[1]) : "r"(addr));
}
__device__ __forceinline__ void mma_bf16(float* c, const uint32_t* a, const uint32_t* b) {
    asm volatile(
        "mma.sync.aligned.m16n8k16.row.col.f32.bf16.bf16.f32 "
        "{%0,%1,%2,%3}, {%4,%5,%6,%7}, {%8,%9}, {%0,%1,%2,%3};"
        : "+f"(c[0]), "+f"(c[1]), "+f"(c[2]), "+f"(c[3])
        : "r"(a[0]), "r"(a[1]), "r"(a[2]), "r"(a[3]), "r"(b[0]), "r"(b[1]));
}
__device__ __forceinline__ float silu(float x) { return x / (1.0f + __expf(-x)); }
__device__ __forceinline__ unsigned short bf_bits(__nv_bfloat16 h) {
    return *reinterpret_cast<unsigned short*>(&h);
}
__device__ __forceinline__ void split8(const float* f, uint4& hq, uint4& lq) {
    __nv_bfloat16* hp = (__nv_bfloat16*)&hq;
    __nv_bfloat16* lp = (__nv_bfloat16*)&lq;
#pragma unroll
    for (int j = 0; j < 8; j++) {
        __nv_bfloat16 h = __float2bfloat16(f[j]);
        hp[j] = h;
        lp[j] = __float2bfloat16(f[j] - __bfloat162float(h));
    }
}

// row stride inside A/B smem tiles: 72 bf16 = 144 bytes (conflict-free ldmatrix)
#define RS 144

// ============================================================================
// k_prep: transpose+split weights. W0 dist rows only (k<128).
// ============================================================================
__global__ void k_prep(const float* __restrict__ w0, const float* __restrict__ w1,
                       const float* __restrict__ w2)
{
    int i = blockIdx.x * blockDim.x + threadIdx.x;
    const int S0 = 128 * 128, S1 = 128 * 128, S2 = 320 * 128;
    if (i < S0) {
        int n = i >> 7, k = i & 127;
        float x = w0[(size_t)k * 128 + n];
        __nv_bfloat16 h = __float2bfloat16(x);
        W0t_hi[i] = h; W0t_lo[i] = __float2bfloat16(x - __bfloat162float(h));
    } else if (i < S0 + S1) {
        int j = i - S0; int n = j >> 7, k = j & 127;
        float x = w1[(size_t)k * 128 + n];
        __nv_bfloat16 h = __float2bfloat16(x);
        W1t_hi[j] = h; W1t_lo[j] = __float2bfloat16(x - __bfloat162float(h));
    } else if (i < S0 + S1 + S2) {
        int j = i - S0 - S1; int n = j >> 7, k = j & 127;
        float x = w2[(size_t)k * 320 + n];
        __nv_bfloat16 h = __float2bfloat16(x);
        W2t_hi[j] = h; W2t_lo[j] = __float2bfloat16(x - __bfloat162float(h));
    }
}

// ============================================================================
// k_pemb: P_src[z][n] = sum_k semb[z][k] * w0[128+k][n]  (fp32, 180 blocks)
// ============================================================================
__global__ __launch_bounds__(128) void k_pemb(
    const float* __restrict__ semb, const float* __restrict__ temb,
    const float* __restrict__ w0)
{
    __shared__ float er[128];
    const int bx = blockIdx.x;
    const int z = (bx < 90) ? bx : bx - 90;
    const int tid = threadIdx.x;
    const float* emb = (bx < 90) ? semb : temb;
    const int off = (bx < 90) ? 128 : 256;
    er[tid] = emb[z * 128 + tid];
    __syncthreads();
    float s = 0.f;
#pragma unroll 8
    for (int k = 0; k < 128; k++)
        s += er[k] * w0[(size_t)(off + k) * 128 + tid];
    float* P = (bx < 90) ? g_Psrc : g_Ptgt;
    P[z * 128 + tid] = s;
}

// ============================================================================
// k_mlp: HMMA GEMM [128 x 128] x [128 x 128] (bf16x3) + bias (+P gathers for
// layer0) + LN + SiLU -> bf16 hi/lo activations.
// 512 threads, 16 warps in 4x4; warp tile 32x32.
// ============================================================================
#define SA_HI 0
#define SA_LO 18432
#define SB_HI 36864
#define SB_LO 55296
#define RED_S 73728
#define RED_Q 75776
#define SBIAS 77824
#define SGAM  78336
#define SBET  78848
#define SZS   79360
#define SZT   79872
#define G_SIZE 80384
#define STGLO_W (36864 / 4)

__global__ __launch_bounds__(512) void k_mlp(
    int layer,
    const int* __restrict__ an, const float* __restrict__ dist,
    const int* __restrict__ ei,
    const float* __restrict__ bias, const float* __restrict__ gamma,
    const float* __restrict__ betap)
{
    extern __shared__ __align__(16) unsigned char sm[];
    const uint32_t sb = smem_u32(sm);
    const int tid = threadIdx.x;
    const int wid = tid >> 5, lane = tid & 31;
    const int gid = lane >> 2, qid = lane & 3;
    const int wid_m = wid >> 2, wid_n = wid & 3;
    const int warpRow = wid_m * 32, warpCol = wid_n * 32;
    const int e0 = blockIdx.x * 128;

    if (tid < 128) {
        ((float*)(sm + SBIAS))[tid] = bias[tid];
        ((float*)(sm + SGAM))[tid]  = gamma[tid];
        ((float*)(sm + SBET))[tid]  = betap[tid];
        if (layer == 0) {
            ((int*)(sm + SZS))[tid] = an[ei[e0 + tid]];
            ((int*)(sm + SZT))[tid] = an[ei[E_EDGES + e0 + tid]];
        }
    }

    float acc[2][4][4];
#pragma unroll
    for (int i = 0; i < 2; i++)
#pragma unroll
        for (int j = 0; j < 4; j++)
#pragma unroll
            for (int c = 0; c < 4; c++) acc[i][j][c] = 0.f;

    const __nv_bfloat16* Bhi = layer ? W1t_hi : W0t_hi;
    const __nv_bfloat16* Blo = layer ? W1t_lo : W0t_lo;

    for (int kc = 0; kc < 2; kc++) {
        __syncthreads();
        // ---- A tile ----
        if (layer == 0) {
            int row = tid >> 2, cg2 = tid & 3;
            const float* sp = dist + (size_t)(e0 + row) * 128 + kc * 64 + cg2 * 16;
            float f[16];
#pragma unroll
            for (int q = 0; q < 4; q++) {
                float4 x = ((const float4*)sp)[q];
                f[q * 4] = x.x; f[q * 4 + 1] = x.y; f[q * 4 + 2] = x.z; f[q * 4 + 3] = x.w;
            }
            uint4 h0, l0, h1, l1;
            split8(f, h0, l0); split8(f + 8, h1, l1);
            uint32_t off = row * RS + cg2 * 32;
            *(uint4*)(sm + SA_HI + off)      = h0;
            *(uint4*)(sm + SA_HI + off + 16) = h1;
            *(uint4*)(sm + SA_LO + off)      = l0;
            *(uint4*)(sm + SA_LO + off + 16) = l1;
        } else {
#pragma unroll
            for (int r = 0; r < 2; r++) {
                int u = tid + r * 512;
                int row = u >> 3, cg = u & 7;
                size_t gi = (size_t)(e0 + row) * 16 + kc * 8 + cg;
                uint32_t off = row * RS + cg * 16;
                *(uint4*)(sm + SA_HI + off) = ((const uint4*)g_h_hi)[gi];
                *(uint4*)(sm + SA_LO + off) = ((const uint4*)g_h_lo)[gi];
            }
        }
        // ---- B tile (weights Wt[n][k]) ----
#pragma unroll
        for (int r = 0; r < 2; r++) {
            int u = tid + r * 512;
            int n = u >> 3, cg = u & 7;
            size_t gi = (size_t)n * 16 + kc * 8 + cg;
            uint32_t off = n * RS + cg * 16;
            *(uint4*)(sm + SB_HI + off) = ((const uint4*)Bhi)[gi];
            *(uint4*)(sm + SB_LO + off) = ((const uint4*)Blo)[gi];
        }
        __syncthreads();

#pragma unroll
        for (int ks = 0; ks < 4; ks++) {
            const int kk = ks * 16;
            const int rA = ((lane >> 3) & 1) * 8 + (lane & 7);
            const int cA = kk + (lane >> 4) * 8;
            uint32_t a_hi[2][4], a_lo[2][4];
#pragma unroll
            for (int i = 0; i < 2; i++) {
                uint32_t ad = sb + (warpRow + i * 16 + rA) * RS + cA * 2;
                ldm4(a_hi[i], ad + SA_HI);
                ldm4(a_lo[i], ad + SA_LO);
            }
            uint32_t b_hi[4][2], b_lo[4][2];
#pragma unroll
            for (int t = 0; t < 2; t++) {
                const int nB = warpCol + t * 16 + ((lane >> 3) & 1) * 8 + (lane & 7);
                const int cB = kk + (lane >> 4) * 8;
                uint32_t bd = sb + nB * RS + cB * 2;
                uint32_t r4[4];
                ldm4(r4, bd + SB_HI);
                b_hi[t * 2][0] = r4[0]; b_hi[t * 2 + 1][0] = r4[1];
                b_hi[t * 2][1] = r4[2]; b_hi[t * 2 + 1][1] = r4[3];
                ldm4(r4, bd + SB_LO);
                b_lo[t * 2][0] = r4[0]; b_lo[t * 2 + 1][0] = r4[1];
                b_lo[t * 2][1] = r4[2]; b_lo[t * 2 + 1][1] = r4[3];
            }
#pragma unroll
            for (int i = 0; i < 2; i++)
#pragma unroll
                for (int j = 0; j < 4; j++) {
                    mma_bf16(acc[i][j], a_hi[i], b_hi[j]);
                    mma_bf16(acc[i][j], a_hi[i], b_lo[j]);
                    mma_bf16(acc[i][j], a_lo[i], b_hi[j]);
                }
        }
    }
    __syncthreads();

    // ---- epilogue: +bias (+P), LN, SiLU, split-store ----
    const float* bs = (const float*)(sm + SBIAS);
    const int* zsA = (const int*)(sm + SZS);
    const int* ztA = (const int*)(sm + SZT);

#pragma unroll
    for (int i = 0; i < 2; i++)
#pragma unroll
        for (int h = 0; h < 2; h++) {
            int row = warpRow + i * 16 + h * 8 + gid;
            const float* ps = layer ? nullptr : (g_Psrc + (size_t)zsA[row] * 128);
            const float* pt = layer ? nullptr : (g_Ptgt + (size_t)ztA[row] * 128);
            float s = 0.f, q = 0.f;
#pragma unroll
            for (int j = 0; j < 4; j++) {
                int col = warpCol + j * 8 + qid * 2;
                float v0 = acc[i][j][2 * h]     + bs[col];
                float v1 = acc[i][j][2 * h + 1] + bs[col + 1];
                if (layer == 0) {
                    float2 a = *(const float2*)(ps + col);
                    float2 b = *(const float2*)(pt + col);
                    v0 += a.x + b.x; v1 += a.y + b.y;
                }
                acc[i][j][2 * h] = v0; acc[i][j][2 * h + 1] = v1;
                s += v0 + v1; q += v0 * v0 + v1 * v1;
            }
            s += __shfl_xor_sync(0xffffffffu, s, 1);
            s += __shfl_xor_sync(0xffffffffu, s, 2);
            q += __shfl_xor_sync(0xffffffffu, q, 1);
            q += __shfl_xor_sync(0xffffffffu, q, 2);
            if (qid == 0) {
                ((float*)(sm + RED_S))[row * 4 + wid_n] = s;
                ((float*)(sm + RED_Q))[row * 4 + wid_n] = q;
            }
        }
    __syncthreads();

    const float* gs  = (const float*)(sm + SGAM);
    const float* bes = (const float*)(sm + SBET);
    uint32_t* stg = (uint32_t*)sm;
#pragma unroll
    for (int i = 0; i < 2; i++)
#pragma unroll
        for (int h = 0; h < 2; h++) {
            int row = warpRow + i * 16 + h * 8 + gid;
            const float* rS = (const float*)(sm + RED_S) + row * 4;
            const float* rQ = (const float*)(sm + RED_Q) + row * 4;
            float st = rS[0] + rS[1] + rS[2] + rS[3];
            float qt = rQ[0] + rQ[1] + rQ[2] + rQ[3];
            float mu   = st * (1.0f / 128.0f);
            float var  = qt * (1.0f / 128.0f) - mu * mu;
            float rinv = rsqrtf(var + 1e-5f);
#pragma unroll
            for (int j = 0; j < 4; j++) {
                int col = warpCol + j * 8 + qid * 2;
                float y0 = silu((acc[i][j][2 * h]     - mu) * rinv * gs[col]     + bes[col]);
                float y1 = silu((acc[i][j][2 * h + 1] - mu) * rinv * gs[col + 1] + bes[col + 1]);
                __nv_bfloat16 h0 = __float2bfloat16(y0), h1 = __float2bfloat16(y1);
                __nv_bfloat16 l0 = __float2bfloat16(y0 - __bfloat162float(h0));
                __nv_bfloat16 l1 = __float2bfloat16(y1 - __bfloat162float(h1));
                int si = row * 65 + (warpCol >> 1) + j * 4 + qid;
                stg[si]           = (uint32_t)bf_bits(h0) | ((uint32_t)bf_bits(h1) << 16);
                stg[STGLO_W + si] = (uint32_t)bf_bits(l0) | ((uint32_t)bf_bits(l1) << 16);
            }
        }
    __syncthreads();
    uint32_t* oh = (uint32_t*)(layer ? g_h2_hi : g_h_hi);
    uint32_t* ol = (uint32_t*)(layer ? g_h2_lo : g_h_lo);
#pragma unroll
    for (int r = 0; r < 16; r++) {
        int idx = tid + r * 512;
        int rr = idx >> 6, w = idx & 63;
        size_t go = (size_t)(e0 + rr) * 64 + w;
        oh[go] = stg[rr * 65 + w];
        ol[go] = stg[STGLO_W + rr * 65 + w];
    }
}

// ============================================================================
// k_out: [128 x 128] x [128 x 160] HMMA bf16x3, +b2, *env*0.2 -> g_y
// grid (2, 1250): blockIdx.x = N tile (L2 reuse of A across adjacent CTAs)
// ============================================================================
#define H_AHI 0
#define H_ALO 18432
#define H_BHI 36864
#define H_BLO 59904
#define H_BIAS 82944
#define H_ENV 83584
#define H_SIZE 84096

__global__ __launch_bounds__(512) void k_out(
    const float* __restrict__ bias, const float* __restrict__ env)
{
    extern __shared__ __align__(16) unsigned char sm[];
    const uint32_t sb = smem_u32(sm);
    const int tid = threadIdx.x;
    const int wid = tid >> 5, lane = tid & 31;
    const int gid = lane >> 2, qid = lane & 3;
    const int wid_m = wid >> 2, wid_n = wid & 3;
    const int warpRow = wid_m * 32, warpCol = wid_n * 40;
    const int e0 = blockIdx.y * 128;
    const int n0 = blockIdx.x * 160;

    if (tid < 160) ((float*)(sm + H_BIAS))[tid] = bias[n0 + tid];
    if (tid < 128) ((float*)(sm + H_ENV))[tid] = env[e0 + tid] * 0.2f;

    float acc[2][5][4];
#pragma unroll
    for (int i = 0; i < 2; i++)
#pragma unroll
        for (int j = 0; j < 5; j++)
#pragma unroll
            for (int c = 0; c < 4; c++) acc[i][j][c] = 0.f;

    for (int kc = 0; kc < 2; kc++) {
        __syncthreads();
#pragma unroll
        for (int r = 0; r < 2; r++) {
            int u = tid + r * 512;
            int row = u >> 3, cg = u & 7;
            size_t gi = (size_t)(e0 + row) * 16 + kc * 8 + cg;
            uint32_t off = row * RS + cg * 16;
            *(uint4*)(sm + H_AHI + off) = ((const uint4*)g_h2_hi)[gi];
            *(uint4*)(sm + H_ALO + off) = ((const uint4*)g_h2_lo)[gi];
        }
        for (int u = tid; u < 1280; u += 512) {
            int n = u >> 3, cg = u & 7;
            size_t gi = (size_t)(n0 + n) * 16 + kc * 8 + cg;
            uint32_t off = n * RS + cg * 16;
            *(uint4*)(sm + H_BHI + off) = ((const uint4*)W2t_hi)[gi];
            *(uint4*)(sm + H_BLO + off) = ((const uint4*)W2t_lo)[gi];
        }
        __syncthreads();

#pragma unroll
        for (int ks = 0; ks < 4; ks++) {
            const int kk = ks * 16;
            const int rA = ((lane >> 3) & 1) * 8 + (lane & 7);
            const int cA = kk + (lane >> 4) * 8;
            uint32_t a_hi[2][4], a_lo[2][4];
#pragma unroll
            for (int i = 0; i < 2; i++) {
                uint32_t ad = sb + (warpRow + i * 16 + rA) * RS + cA * 2;
                ldm4(a_hi[i], ad + H_AHI);
                ldm4(a_lo[i], ad + H_ALO);
            }
            uint32_t b_hi[5][2], b_lo[5][2];
#pragma unroll
            for (int t = 0; t < 2; t++) {
                const int nB = warpCol + t * 16 + ((lane >> 3) & 1) * 8 + (lane & 7);
                const int cB = kk + (lane >> 4) * 8;
                uint32_t bd = sb + nB * RS + cB * 2;
                uint32_t r4[4];
                ldm4(r4, bd + H_BHI);
                b_hi[t * 2][0] = r4[0]; b_hi[t * 2 + 1][0] = r4[1];
                b_hi[t * 2][1] = r4[2]; b_hi[t * 2 + 1][1] = r4[3];
                ldm4(r4, bd + H_BLO);
                b_lo[t * 2][0] = r4[0]; b_lo[t * 2 + 1][0] = r4[1];
                b_lo[t * 2][1] = r4[2]; b_lo[t * 2 + 1][1] = r4[3];
            }
            {
                const int nB = warpCol + 32 + (lane & 7);
                const int cB = kk + ((lane >> 3) & 1) * 8;
                uint32_t bd = sb + nB * RS + cB * 2;
                ldm2(b_hi[4], bd + H_BHI);
                ldm2(b_lo[4], bd + H_BLO);
            }
#pragma unroll
            for (int i = 0; i < 2; i++)
#pragma unroll
                for (int j = 0; j < 5; j++) {
                    mma_bf16(acc[i][j], a_hi[i], b_hi[j]);
                    mma_bf16(acc[i][j], a_hi[i], b_lo[j]);
                    mma_bf16(acc[i][j], a_lo[i], b_hi[j]);
                }
        }
    }

    const float* bsp = (const float*)(sm + H_BIAS);
    const float* ep  = (const float*)(sm + H_ENV);
#pragma unroll
    for (int i = 0; i < 2; i++)
#pragma unroll
        for (int h = 0; h < 2; h++) {
            int row = warpRow + i * 16 + h * 8 + gid;
            float es = ep[row];
            float* yp = g_y + (size_t)(e0 + row) * 320 + n0;
#pragma unroll
            for (int j = 0; j < 5; j++) {
                int col = warpCol + j * 8 + qid * 2;
                float2 o;
                o.x = (acc[i][j][2 * h]     + bsp[col])     * es;
                o.y = (acc[i][j][2 * h + 1] + bsp[col + 1]) * es;
                *(float2*)(yp + col) = o;
            }
        }
}

// ============================================================================
// counting sort by target node
// ============================================================================
__global__ void k_zero_hist() {
    int i = blockIdx.x * blockDim.x + threadIdx.x;
    if (i < NNODES) g_hist[i] = 0;
}
__global__ void k_hist(const int* __restrict__ ei) {
    int e = blockIdx.x * blockDim.x + threadIdx.x;
    if (e < E_EDGES) atomicAdd(&g_hist[ei[E_EDGES + e]], 1);
}
__global__ __launch_bounds__(1024) void k_scan() {
    __shared__ int part[1024];
    const int tid = threadIdx.x;
    const int base = tid * 10;
    int local[10];
    int s = 0;
#pragma unroll
    for (int j = 0; j < 10; j++) {
        int idx = base + j;
        int h = (idx < NNODES) ? g_hist[idx] : 0;
        local[j] = s; s += h;
    }
    part[tid] = s;
    __syncthreads();
    for (int o = 1; o < 1024; o <<= 1) {
        int v = 0;
        if (tid >= o) v = part[tid - o];
        __syncthreads();
        part[tid] += v;
        __syncthreads();
    }
    int prev = (tid == 0) ? 0 : part[tid - 1];
#pragma unroll
    for (int j = 0; j < 10; j++) {
        int idx = base + j;
        if (idx < NNODES) { g_off[idx] = prev + local[j]; g_cur[idx] = prev + local[j]; }
    }
    if (tid == 1023) g_off[NNODES] = prev + s;
}
__global__ void k_scatter(const int* __restrict__ ei) {
    int e = blockIdx.x * blockDim.x + threadIdx.x;
    if (e < E_EDGES) {
        int t = ei[E_EDGES + e];
        int p = atomicAdd(&g_cur[t], 1);
        g_order[p] = e;
    }
}

// ============================================================================
// k_wigner: per-node rotate + segment sum. 320 threads; register accumulators.
// thread owns (c = tid&63, mg = tid>>6); acc[jm] covers m = mg*5+jm.
// ============================================================================
#define WB 8
__global__ __launch_bounds__(320) void k_wigner(
    const float* __restrict__ wig, float* __restrict__ out)
{
    const int node = blockIdx.x;
    const int tid  = threadIdx.x;
    const int c = tid & 63, mg = tid >> 6;
    __shared__ __align__(16) float ys[WB * 320];
    __shared__ float sw[WB * 128];

    float acc[5] = {0.f, 0.f, 0.f, 0.f, 0.f};
    const int beg = g_off[node];
    const int end = g_off[node + 1];

    for (int p = beg; p < end; p += WB) {
        const int nb = min(WB, end - p);
        __syncthreads();
#pragma unroll
        for (int r = 0; r < 2; r++) {
            int v = tid + r * 320;              // 0..639
            int j = v / 80, idx = v - j * 80;   // 80 float4 per edge
            if (j < nb) {
                int e = g_order[p + j];
                ((float4*)ys)[j * 80 + idx] =
                    ((const float4*)(g_y + (size_t)e * 320))[idx];
            }
        }
        if (tid < 200) {
            int j = tid / 25, m = tid - j * 25;
            if (j < nb) {
                int e = g_order[p + j];
                const float* wp = wig + (size_t)e * 625 + m * 25;
                float* dp = sw + j * 128 + m * 5;
                dp[0] = wp[0]; dp[1] = wp[1]; dp[2] = wp[2];
                dp[3] = wp[3]; dp[4] = wp[4];
            }
        }
        __syncthreads();
        for (int j = 0; j < nb; j++) {
            const float* yy = ys + j * 320;
            float y0 = yy[c], y1 = yy[64 + c], y2 = yy[128 + c],
                  y3 = yy[192 + c], y4 = yy[256 + c];
            const float* wj = sw + j * 128 + mg * 25;
#pragma unroll
            for (int jm = 0; jm < 5; jm++) {
                const float* w = wj + jm * 5;
                acc[jm] += w[0] * y0 + w[1] * y1 + w[2] * y2 + w[3] * y3 + w[4] * y4;
            }
        }
    }
    float* op = out + (size_t)node * 1600;
#pragma unroll
    for (int jm = 0; jm < 5; jm++)
        op[(mg * 5 + jm) * 64 + c] = acc[jm];
}

// ============================================================================
extern "C" void kernel_launch(void* const* d_in, const int* in_sizes, int n_in,
                              void* d_out, int out_size)
{
    const int*   an   = (const int*)  d_in[0];
    const float* dist = (const float*)d_in[1];
    const int*   ei   = (const int*)  d_in[2];
    const float* env  = (const float*)d_in[3];
    const float* semb = (const float*)d_in[4];
    const float* temb = (const float*)d_in[5];
    const float* w0   = (const float*)d_in[6];
    const float* b0   = (const float*)d_in[7];
    const float* g0   = (const float*)d_in[8];
    const float* be0  = (const float*)d_in[9];
    const float* w1   = (const float*)d_in[10];
    const float* b1   = (const float*)d_in[11];
    const float* g1   = (const float*)d_in[12];
    const float* be1  = (const float*)d_in[13];
    const float* w2   = (const float*)d_in[14];
    const float* b2   = (const float*)d_in[15];
    const float* wig  = (const float*)d_in[16];
    float* out = (float*)d_out;

    cudaFuncSetAttribute(k_mlp, cudaFuncAttributeMaxDynamicSharedMemorySize, G_SIZE);
    cudaFuncSetAttribute(k_out, cudaFuncAttributeMaxDynamicSharedMemorySize, H_SIZE);

    // launch #4 gets profiled by the harness's ncu capture -> put k_mlp(0) there
    k_prep     <<<(128 * 128 * 2 + 320 * 128 + 255) / 256, 256>>>(w0, w1, w2);
    k_pemb     <<<180, 128>>>(semb, temb, w0);
    k_zero_hist<<<(NNODES + 255) / 256, 256>>>();
    k_mlp<<<E_EDGES / 128, 512, G_SIZE>>>(0, an, dist, ei, b0, g0, be0);
    k_hist     <<<E_EDGES / 256, 256>>>(ei);
    k_scan     <<<1, 1024>>>();
    k_scatter  <<<E_EDGES / 256, 256>>>(ei);
    k_mlp<<<E_EDGES / 128, 512, G_SIZE>>>(1, an, dist, ei, b1, g1, be1);
    k_out<<<dim3(2, E_EDGES / 128), 512, H_SIZE>>>(b2, env);
    k_wigner<<<NNODES, 320>>>(wig, out);
}

// round 6
// speedup vs baseline: 1.9183x; 1.1584x over previous
#include <cuda_runtime.h>
#include <cuda_bf16.h>
#include <cstdint>

#define E_EDGES 160000
#define NNODES  10000

// ---------------- scratch (device globals) ----------------
__device__ __align__(16) __nv_bfloat16 g_h_hi [E_EDGES * 128];
__device__ __align__(16) __nv_bfloat16 g_h_lo [E_EDGES * 128];
__device__ __align__(16) __nv_bfloat16 g_h2_hi[E_EDGES * 128];
__device__ __align__(16) __nv_bfloat16 g_h2_lo[E_EDGES * 128];
__device__ __align__(16) float g_y [E_EDGES * 320];
// transposed split weights Wt[n][k]
__device__ __align__(16) __nv_bfloat16 W0t_hi[128 * 128];   // dist part only
__device__ __align__(16) __nv_bfloat16 W0t_lo[128 * 128];
__device__ __align__(16) __nv_bfloat16 W1t_hi[128 * 128];
__device__ __align__(16) __nv_bfloat16 W1t_lo[128 * 128];
__device__ __align__(16) __nv_bfloat16 W2t_hi[320 * 128];
__device__ __align__(16) __nv_bfloat16 W2t_lo[320 * 128];
// precomputed embedding projections (fp32 exact)
__device__ __align__(16) float g_Psrc[90 * 128];
__device__ __align__(16) float g_Ptgt[90 * 128];
__device__ int g_hist [NNODES];
__device__ int g_off  [NNODES + 1];
__device__ int g_cur  [NNODES];
__device__ int g_order[E_EDGES];

// ---------------- helpers ----------------
__device__ __forceinline__ uint32_t smem_u32(const void* p) {
    uint32_t a;
    asm("{ .reg .u64 t; cvta.to.shared.u64 t, %1; cvt.u32.u64 %0, t; }" : "=r"(a) : "l"(p));
    return a;
}
__device__ __forceinline__ void ldm4(uint32_t* r, uint32_t addr) {
    asm volatile("ldmatrix.sync.aligned.m8n8.x4.shared.b16 {%0,%1,%2,%3}, [%4];"
                 : "=r"(r[0]), "=r"(r[1]), "=r"(r[2]), "=r"(r[3]) : "r"(addr));
}
__device__ __forceinline__ void ldm2(uint32_t* r, uint32_t addr) {
    asm volatile("ldmatrix.sync.aligned.m8n8.x2.shared.b16 {%0,%1}, [%2];"
                 : "=r"(r[0]), "=r"(r[1]) : "r"(addr));
}
__device__ __forceinline__ void mma_bf16(float* c, const uint32_t* a, const uint32_t* b) {
    asm volatile(
        "mma.sync.aligned.m16n8k16.row.col.f32.bf16.bf16.f32 "
        "{%0,%1,%2,%3}, {%4,%5,%6,%7}, {%8,%9}, {%0,%1,%2,%3};"
        : "+f"(c[0]), "+f"(c[1]), "+f"(c[2]), "+f"(c[3])
        : "r"(a[0]), "r"(a[1]), "r"(a[2]), "r"(a[3]), "r"(b[0]), "r"(b[1]));
}
__device__ __forceinline__ float silu(float x) { return x / (1.0f + __expf(-x)); }
__device__ __forceinline__ unsigned short bf_bits(__nv_bfloat16 h) {
    return *reinterpret_cast<unsigned short*>(&h);
}
__device__ __forceinline__ void split8(const float* f, uint4& hq, uint4& lq) {
    __nv_bfloat16* hp = (__nv_bfloat16*)&hq;
    __nv_bfloat16* lp = (__nv_bfloat16*)&lq;
#pragma unroll
    for (int j = 0; j < 8; j++) {
        __nv_bfloat16 h = __float2bfloat16(f[j]);
        hp[j] = h;
        lp[j] = __float2bfloat16(f[j] - __bfloat162float(h));
    }
}

// row stride inside A/B smem tiles: 72 bf16 = 144 bytes (conflict-free ldmatrix)
#define RS 144

// ============================================================================
// k_prep: transpose+split weights. W0 dist rows only (k<128).
// ============================================================================
__global__ void k_prep(const float* __restrict__ w0, const float* __restrict__ w1,
                       const float* __restrict__ w2)
{
    int i = blockIdx.x * blockDim.x + threadIdx.x;
    const int S0 = 128 * 128, S1 = 128 * 128, S2 = 320 * 128;
    if (i < S0) {
        int n = i >> 7, k = i & 127;
        float x = w0[(size_t)k * 128 + n];
        __nv_bfloat16 h = __float2bfloat16(x);
        W0t_hi[i] = h; W0t_lo[i] = __float2bfloat16(x - __bfloat162float(h));
    } else if (i < S0 + S1) {
        int j = i - S0; int n = j >> 7, k = j & 127;
        float x = w1[(size_t)k * 128 + n];
        __nv_bfloat16 h = __float2bfloat16(x);
        W1t_hi[j] = h; W1t_lo[j] = __float2bfloat16(x - __bfloat162float(h));
    } else if (i < S0 + S1 + S2) {
        int j = i - S0 - S1; int n = j >> 7, k = j & 127;
        float x = w2[(size_t)k * 320 + n];
        __nv_bfloat16 h = __float2bfloat16(x);
        W2t_hi[j] = h; W2t_lo[j] = __float2bfloat16(x - __bfloat162float(h));
    }
}

// ============================================================================
// k_pemb: P_src[z][n] = sum_k semb[z][k] * w0[128+k][n]  (fp32, 180 blocks)
// ============================================================================
__global__ __launch_bounds__(128) void k_pemb(
    const float* __restrict__ semb, const float* __restrict__ temb,
    const float* __restrict__ w0)
{
    __shared__ float er[128];
    const int bx = blockIdx.x;
    const int z = (bx < 90) ? bx : bx - 90;
    const int tid = threadIdx.x;
    const float* emb = (bx < 90) ? semb : temb;
    const int off = (bx < 90) ? 128 : 256;
    er[tid] = emb[z * 128 + tid];
    __syncthreads();
    float s = 0.f;
#pragma unroll 8
    for (int k = 0; k < 128; k++)
        s += er[k] * w0[(size_t)(off + k) * 128 + tid];
    float* P = (bx < 90) ? g_Psrc : g_Ptgt;
    P[z * 128 + tid] = s;
}

// ============================================================================
// k_mlp: HMMA GEMM [64 x 128] x [128 x 128] (bf16x3) + bias (+P) + LN + SiLU.
// 256 threads, 8 warps 2x4; warp tile 32x32. 2 CTAs/SM for latency overlap.
// ============================================================================
#define SA_HI 0
#define SA_LO 9216
#define SB_HI 18432
#define SB_LO 36864
#define RED_S 55296
#define RED_Q 56320
#define SBIAS 57344
#define SGAM  57856
#define SBET  58368
#define SZS   58880
#define SZT   59136
#define G_SIZE 59392
#define STGLO_W 4160    // staging lo starts at word 4160 (byte 16640)

__global__ __launch_bounds__(256) void k_mlp(
    int layer,
    const int* __restrict__ an, const float* __restrict__ dist,
    const int* __restrict__ ei,
    const float* __restrict__ bias, const float* __restrict__ gamma,
    const float* __restrict__ betap)
{
    extern __shared__ __align__(16) unsigned char sm[];
    const uint32_t sb = smem_u32(sm);
    const int tid = threadIdx.x;
    const int wid = tid >> 5, lane = tid & 31;
    const int gid = lane >> 2, qid = lane & 3;
    const int wid_m = wid >> 2, wid_n = wid & 3;
    const int warpRow = wid_m * 32, warpCol = wid_n * 32;
    const int e0 = blockIdx.x * 64;

    if (tid < 128) {
        ((float*)(sm + SBIAS))[tid] = bias[tid];
        ((float*)(sm + SGAM))[tid]  = gamma[tid];
        ((float*)(sm + SBET))[tid]  = betap[tid];
    }
    if (layer == 0 && tid < 64) {
        ((int*)(sm + SZS))[tid] = an[ei[e0 + tid]];
        ((int*)(sm + SZT))[tid] = an[ei[E_EDGES + e0 + tid]];
    }

    float acc[2][4][4];
#pragma unroll
    for (int i = 0; i < 2; i++)
#pragma unroll
        for (int j = 0; j < 4; j++)
#pragma unroll
            for (int c = 0; c < 4; c++) acc[i][j][c] = 0.f;

    const __nv_bfloat16* Bhi = layer ? W1t_hi : W0t_hi;
    const __nv_bfloat16* Blo = layer ? W1t_lo : W0t_lo;

    for (int kc = 0; kc < 2; kc++) {
        __syncthreads();
        // ---- A tile: 64 rows x 64 cols ----
        if (layer == 0) {
            int row = tid >> 2, cg2 = tid & 3;
            const float* sp = dist + (size_t)(e0 + row) * 128 + kc * 64 + cg2 * 16;
            float f[16];
#pragma unroll
            for (int q = 0; q < 4; q++) {
                float4 x = ((const float4*)sp)[q];
                f[q * 4] = x.x; f[q * 4 + 1] = x.y; f[q * 4 + 2] = x.z; f[q * 4 + 3] = x.w;
            }
            uint4 h0, l0, h1, l1;
            split8(f, h0, l0); split8(f + 8, h1, l1);
            uint32_t off = row * RS + cg2 * 32;
            *(uint4*)(sm + SA_HI + off)      = h0;
            *(uint4*)(sm + SA_HI + off + 16) = h1;
            *(uint4*)(sm + SA_LO + off)      = l0;
            *(uint4*)(sm + SA_LO + off + 16) = l1;
        } else {
            int row = tid >> 2, cg = (tid & 3) * 2;
            size_t gi = (size_t)(e0 + row) * 16 + kc * 8 + cg;
            uint32_t off = row * RS + cg * 16;
            *(uint4*)(sm + SA_HI + off)      = ((const uint4*)g_h_hi)[gi];
            *(uint4*)(sm + SA_HI + off + 16) = ((const uint4*)g_h_hi)[gi + 1];
            *(uint4*)(sm + SA_LO + off)      = ((const uint4*)g_h_lo)[gi];
            *(uint4*)(sm + SA_LO + off + 16) = ((const uint4*)g_h_lo)[gi + 1];
        }
        // ---- B tile: 128 n-rows x 64 cols ----
#pragma unroll
        for (int r = 0; r < 4; r++) {
            int u = tid + r * 256;
            int n = u >> 3, cg = u & 7;
            size_t gi = (size_t)n * 16 + kc * 8 + cg;
            uint32_t off = n * RS + cg * 16;
            *(uint4*)(sm + SB_HI + off) = ((const uint4*)Bhi)[gi];
            *(uint4*)(sm + SB_LO + off) = ((const uint4*)Blo)[gi];
        }
        __syncthreads();

#pragma unroll
        for (int ks = 0; ks < 4; ks++) {
            const int kk = ks * 16;
            const int rA = ((lane >> 3) & 1) * 8 + (lane & 7);
            const int cA = kk + (lane >> 4) * 8;
            uint32_t a_hi[2][4], a_lo[2][4];
#pragma unroll
            for (int i = 0; i < 2; i++) {
                uint32_t ad = sb + (warpRow + i * 16 + rA) * RS + cA * 2;
                ldm4(a_hi[i], ad + SA_HI);
                ldm4(a_lo[i], ad + SA_LO);
            }
            uint32_t b_hi[4][2], b_lo[4][2];
#pragma unroll
            for (int t = 0; t < 2; t++) {
                const int nB = warpCol + t * 16 + ((lane >> 3) & 1) * 8 + (lane & 7);
                const int cB = kk + (lane >> 4) * 8;
                uint32_t bd = sb + nB * RS + cB * 2;
                uint32_t r4[4];
                ldm4(r4, bd + SB_HI);
                b_hi[t * 2][0] = r4[0]; b_hi[t * 2 + 1][0] = r4[1];
                b_hi[t * 2][1] = r4[2]; b_hi[t * 2 + 1][1] = r4[3];
                ldm4(r4, bd + SB_LO);
                b_lo[t * 2][0] = r4[0]; b_lo[t * 2 + 1][0] = r4[1];
                b_lo[t * 2][1] = r4[2]; b_lo[t * 2 + 1][1] = r4[3];
            }
#pragma unroll
            for (int i = 0; i < 2; i++)
#pragma unroll
                for (int j = 0; j < 4; j++) {
                    mma_bf16(acc[i][j], a_hi[i], b_hi[j]);
                    mma_bf16(acc[i][j], a_hi[i], b_lo[j]);
                    mma_bf16(acc[i][j], a_lo[i], b_hi[j]);
                }
        }
    }
    __syncthreads();

    // ---- epilogue: +bias (+P), LN, SiLU, split-store ----
    const float* bs = (const float*)(sm + SBIAS);
    const int* zsA = (const int*)(sm + SZS);
    const int* ztA = (const int*)(sm + SZT);

#pragma unroll
    for (int i = 0; i < 2; i++)
#pragma unroll
        for (int h = 0; h < 2; h++) {
            int row = warpRow + i * 16 + h * 8 + gid;
            const float* ps = layer ? nullptr : (g_Psrc + (size_t)zsA[row] * 128);
            const float* pt = layer ? nullptr : (g_Ptgt + (size_t)ztA[row] * 128);
            float s = 0.f, q = 0.f;
#pragma unroll
            for (int j = 0; j < 4; j++) {
                int col = warpCol + j * 8 + qid * 2;
                float v0 = acc[i][j][2 * h]     + bs[col];
                float v1 = acc[i][j][2 * h + 1] + bs[col + 1];
                if (layer == 0) {
                    float2 a = *(const float2*)(ps + col);
                    float2 b = *(const float2*)(pt + col);
                    v0 += a.x + b.x; v1 += a.y + b.y;
                }
                acc[i][j][2 * h] = v0; acc[i][j][2 * h + 1] = v1;
                s += v0 + v1; q += v0 * v0 + v1 * v1;
            }
            s += __shfl_xor_sync(0xffffffffu, s, 1);
            s += __shfl_xor_sync(0xffffffffu, s, 2);
            q += __shfl_xor_sync(0xffffffffu, q, 1);
            q += __shfl_xor_sync(0xffffffffu, q, 2);
            if (qid == 0) {
                ((float*)(sm + RED_S))[row * 4 + wid_n] = s;
                ((float*)(sm + RED_Q))[row * 4 + wid_n] = q;
            }
        }
    __syncthreads();

    const float* gs  = (const float*)(sm + SGAM);
    const float* bes = (const float*)(sm + SBET);
    uint32_t* stg = (uint32_t*)sm;
#pragma unroll
    for (int i = 0; i < 2; i++)
#pragma unroll
        for (int h = 0; h < 2; h++) {
            int row = warpRow + i * 16 + h * 8 + gid;
            const float* rS = (const float*)(sm + RED_S) + row * 4;
            const float* rQ = (const float*)(sm + RED_Q) + row * 4;
            float st = rS[0] + rS[1] + rS[2] + rS[3];
            float qt = rQ[0] + rQ[1] + rQ[2] + rQ[3];
            float mu   = st * (1.0f / 128.0f);
            float var  = qt * (1.0f / 128.0f) - mu * mu;
            float rinv = rsqrtf(var + 1e-5f);
#pragma unroll
            for (int j = 0; j < 4; j++) {
                int col = warpCol + j * 8 + qid * 2;
                float y0 = silu((acc[i][j][2 * h]     - mu) * rinv * gs[col]     + bes[col]);
                float y1 = silu((acc[i][j][2 * h + 1] - mu) * rinv * gs[col + 1] + bes[col + 1]);
                __nv_bfloat16 h0 = __float2bfloat16(y0), h1 = __float2bfloat16(y1);
                __nv_bfloat16 l0 = __float2bfloat16(y0 - __bfloat162float(h0));
                __nv_bfloat16 l1 = __float2bfloat16(y1 - __bfloat162float(h1));
                int si = row * 65 + (warpCol >> 1) + j * 4 + qid;
                stg[si]           = (uint32_t)bf_bits(h0) | ((uint32_t)bf_bits(h1) << 16);
                stg[STGLO_W + si] = (uint32_t)bf_bits(l0) | ((uint32_t)bf_bits(l1) << 16);
            }
        }
    __syncthreads();
    uint32_t* oh = (uint32_t*)(layer ? g_h2_hi : g_h_hi);
    uint32_t* ol = (uint32_t*)(layer ? g_h2_lo : g_h_lo);
#pragma unroll
    for (int r = 0; r < 16; r++) {
        int idx = tid + r * 256;
        int rr = idx >> 6, w = idx & 63;
        size_t go = (size_t)(e0 + rr) * 64 + w;
        oh[go] = stg[rr * 65 + w];
        ol[go] = stg[STGLO_W + rr * 65 + w];
    }
}

// ============================================================================
// k_out: [64 x 128] x [128 x 160] HMMA bf16x3, +b2, *env*0.2 -> g_y
// grid (2, 2500); 256 threads, 8 warps 2x4; warp tile 32x40. 2 CTAs/SM.
// ============================================================================
#define H_AHI 0
#define H_ALO 9216
#define H_BHI 18432
#define H_BLO 41472
#define H_BIAS 64512
#define H_ENV 65152
#define H_SIZE 65536

__global__ __launch_bounds__(256) void k_out(
    const float* __restrict__ bias, const float* __restrict__ env)
{
    extern __shared__ __align__(16) unsigned char sm[];
    const uint32_t sb = smem_u32(sm);
    const int tid = threadIdx.x;
    const int wid = tid >> 5, lane = tid & 31;
    const int gid = lane >> 2, qid = lane & 3;
    const int wid_m = wid >> 2, wid_n = wid & 3;
    const int warpRow = wid_m * 32, warpCol = wid_n * 40;
    const int e0 = blockIdx.y * 64;
    const int n0 = blockIdx.x * 160;

    if (tid < 160) ((float*)(sm + H_BIAS))[tid] = bias[n0 + tid];
    if (tid < 64)  ((float*)(sm + H_ENV))[tid] = env[e0 + tid] * 0.2f;

    float acc[2][5][4];
#pragma unroll
    for (int i = 0; i < 2; i++)
#pragma unroll
        for (int j = 0; j < 5; j++)
#pragma unroll
            for (int c = 0; c < 4; c++) acc[i][j][c] = 0.f;

    for (int kc = 0; kc < 2; kc++) {
        __syncthreads();
        {   // A tile: 64 rows
            int row = tid >> 2, cg = (tid & 3) * 2;
            size_t gi = (size_t)(e0 + row) * 16 + kc * 8 + cg;
            uint32_t off = row * RS + cg * 16;
            *(uint4*)(sm + H_AHI + off)      = ((const uint4*)g_h2_hi)[gi];
            *(uint4*)(sm + H_AHI + off + 16) = ((const uint4*)g_h2_hi)[gi + 1];
            *(uint4*)(sm + H_ALO + off)      = ((const uint4*)g_h2_lo)[gi];
            *(uint4*)(sm + H_ALO + off + 16) = ((const uint4*)g_h2_lo)[gi + 1];
        }
#pragma unroll
        for (int r = 0; r < 5; r++) {
            int u = tid + r * 256;
            int n = u >> 3, cg = u & 7;
            size_t gi = (size_t)(n0 + n) * 16 + kc * 8 + cg;
            uint32_t off = n * RS + cg * 16;
            *(uint4*)(sm + H_BHI + off) = ((const uint4*)W2t_hi)[gi];
            *(uint4*)(sm + H_BLO + off) = ((const uint4*)W2t_lo)[gi];
        }
        __syncthreads();

#pragma unroll
        for (int ks = 0; ks < 4; ks++) {
            const int kk = ks * 16;
            const int rA = ((lane >> 3) & 1) * 8 + (lane & 7);
            const int cA = kk + (lane >> 4) * 8;
            uint32_t a_hi[2][4], a_lo[2][4];
#pragma unroll
            for (int i = 0; i < 2; i++) {
                uint32_t ad = sb + (warpRow + i * 16 + rA) * RS + cA * 2;
                ldm4(a_hi[i], ad + H_AHI);
                ldm4(a_lo[i], ad + H_ALO);
            }
            uint32_t b_hi[5][2], b_lo[5][2];
#pragma unroll
            for (int t = 0; t < 2; t++) {
                const int nB = warpCol + t * 16 + ((lane >> 3) & 1) * 8 + (lane & 7);
                const int cB = kk + (lane >> 4) * 8;
                uint32_t bd = sb + nB * RS + cB * 2;
                uint32_t r4[4];
                ldm4(r4, bd + H_BHI);
                b_hi[t * 2][0] = r4[0]; b_hi[t * 2 + 1][0] = r4[1];
                b_hi[t * 2][1] = r4[2]; b_hi[t * 2 + 1][1] = r4[3];
                ldm4(r4, bd + H_BLO);
                b_lo[t * 2][0] = r4[0]; b_lo[t * 2 + 1][0] = r4[1];
                b_lo[t * 2][1] = r4[2]; b_lo[t * 2 + 1][1] = r4[3];
            }
            {
                const int nB = warpCol + 32 + (lane & 7);
                const int cB = kk + ((lane >> 3) & 1) * 8;
                uint32_t bd = sb + nB * RS + cB * 2;
                ldm2(b_hi[4], bd + H_BHI);
                ldm2(b_lo[4], bd + H_BLO);
            }
#pragma unroll
            for (int i = 0; i < 2; i++)
#pragma unroll
                for (int j = 0; j < 5; j++) {
                    mma_bf16(acc[i][j], a_hi[i], b_hi[j]);
                    mma_bf16(acc[i][j], a_hi[i], b_lo[j]);
                    mma_bf16(acc[i][j], a_lo[i], b_hi[j]);
                }
        }
    }

    const float* bsp = (const float*)(sm + H_BIAS);
    const float* ep  = (const float*)(sm + H_ENV);
#pragma unroll
    for (int i = 0; i < 2; i++)
#pragma unroll
        for (int h = 0; h < 2; h++) {
            int row = warpRow + i * 16 + h * 8 + gid;
            float es = ep[row];
            float* yp = g_y + (size_t)(e0 + row) * 320 + n0;
#pragma unroll
            for (int j = 0; j < 5; j++) {
                int col = warpCol + j * 8 + qid * 2;
                float2 o;
                o.x = (acc[i][j][2 * h]     + bsp[col])     * es;
                o.y = (acc[i][j][2 * h + 1] + bsp[col + 1]) * es;
                *(float2*)(yp + col) = o;
            }
        }
}

// ============================================================================
// counting sort by target node
// ============================================================================
__global__ void k_zero_hist() {
    int i = blockIdx.x * blockDim.x + threadIdx.x;
    if (i < NNODES) g_hist[i] = 0;
}
__global__ void k_hist(const int* __restrict__ ei) {
    int e = blockIdx.x * blockDim.x + threadIdx.x;
    if (e < E_EDGES) atomicAdd(&g_hist[ei[E_EDGES + e]], 1);
}
__global__ __launch_bounds__(1024) void k_scan() {
    __shared__ int part[1024];
    const int tid = threadIdx.x;
    const int base = tid * 10;
    int local[10];
    int s = 0;
#pragma unroll
    for (int j = 0; j < 10; j++) {
        int idx = base + j;
        int h = (idx < NNODES) ? g_hist[idx] : 0;
        local[j] = s; s += h;
    }
    part[tid] = s;
    __syncthreads();
    for (int o = 1; o < 1024; o <<= 1) {
        int v = 0;
        if (tid >= o) v = part[tid - o];
        __syncthreads();
        part[tid] += v;
        __syncthreads();
    }
    int prev = (tid == 0) ? 0 : part[tid - 1];
#pragma unroll
    for (int j = 0; j < 10; j++) {
        int idx = base + j;
        if (idx < NNODES) { g_off[idx] = prev + local[j]; g_cur[idx] = prev + local[j]; }
    }
    if (tid == 1023) g_off[NNODES] = prev + s;
}
__global__ void k_scatter(const int* __restrict__ ei) {
    int e = blockIdx.x * blockDim.x + threadIdx.x;
    if (e < E_EDGES) {
        int t = ei[E_EDGES + e];
        int p = atomicAdd(&g_cur[t], 1);
        g_order[p] = e;
    }
}

// ============================================================================
// k_wigner: per-node rotate + segment sum. 320 threads; register accumulators.
// ============================================================================
#define WB 8
__global__ __launch_bounds__(320) void k_wigner(
    const float* __restrict__ wig, float* __restrict__ out)
{
    const int node = blockIdx.x;
    const int tid  = threadIdx.x;
    const int c = tid & 63, mg = tid >> 6;
    __shared__ __align__(16) float ys[WB * 320];
    __shared__ float sw[WB * 128];

    float acc[5] = {0.f, 0.f, 0.f, 0.f, 0.f};
    const int beg = g_off[node];
    const int end = g_off[node + 1];

    for (int p = beg; p < end; p += WB) {
        const int nb = min(WB, end - p);
        __syncthreads();
#pragma unroll
        for (int r = 0; r < 2; r++) {
            int v = tid + r * 320;
            int j = v / 80, idx = v - j * 80;
            if (j < nb) {
                int e = g_order[p + j];
                ((float4*)ys)[j * 80 + idx] =
                    ((const float4*)(g_y + (size_t)e * 320))[idx];
            }
        }
        if (tid < 200) {
            int j = tid / 25, m = tid - j * 25;
            if (j < nb) {
                int e = g_order[p + j];
                const float* wp = wig + (size_t)e * 625 + m * 25;
                float* dp = sw + j * 128 + m * 5;
                dp[0] = wp[0]; dp[1] = wp[1]; dp[2] = wp[2];
                dp[3] = wp[3]; dp[4] = wp[4];
            }
        }
        __syncthreads();
        for (int j = 0; j < nb; j++) {
            const float* yy = ys + j * 320;
            float y0 = yy[c], y1 = yy[64 + c], y2 = yy[128 + c],
                  y3 = yy[192 + c], y4 = yy[256 + c];
            const float* wj = sw + j * 128 + mg * 25;
#pragma unroll
            for (int jm = 0; jm < 5; jm++) {
                const float* w = wj + jm * 5;
                acc[jm] += w[0] * y0 + w[1] * y1 + w[2] * y2 + w[3] * y3 + w[4] * y4;
            }
        }
    }
    float* op = out + (size_t)node * 1600;
#pragma unroll
    for (int jm = 0; jm < 5; jm++)
        op[(mg * 5 + jm) * 64 + c] = acc[jm];
}

// ============================================================================
extern "C" void kernel_launch(void* const* d_in, const int* in_sizes, int n_in,
                              void* d_out, int out_size)
{
    const int*   an   = (const int*)  d_in[0];
    const float* dist = (const float*)d_in[1];
    const int*   ei   = (const int*)  d_in[2];
    const float* env  = (const float*)d_in[3];
    const float* semb = (const float*)d_in[4];
    const float* temb = (const float*)d_in[5];
    const float* w0   = (const float*)d_in[6];
    const float* b0   = (const float*)d_in[7];
    const float* g0   = (const float*)d_in[8];
    const float* be0  = (const float*)d_in[9];
    const float* w1   = (const float*)d_in[10];
    const float* b1   = (const float*)d_in[11];
    const float* g1   = (const float*)d_in[12];
    const float* be1  = (const float*)d_in[13];
    const float* w2   = (const float*)d_in[14];
    const float* b2   = (const float*)d_in[15];
    const float* wig  = (const float*)d_in[16];
    float* out = (float*)d_out;

    cudaFuncSetAttribute(k_mlp, cudaFuncAttributeMaxDynamicSharedMemorySize, G_SIZE);
    cudaFuncSetAttribute(k_out, cudaFuncAttributeMaxDynamicSharedMemorySize, H_SIZE);

    // launch #4 gets profiled by the harness's ncu capture -> put k_mlp(0) there
    k_prep     <<<(128 * 128 * 2 + 320 * 128 + 255) / 256, 256>>>(w0, w1, w2);
    k_pemb     <<<180, 128>>>(semb, temb, w0);
    k_zero_hist<<<(NNODES + 255) / 256, 256>>>();
    k_mlp<<<E_EDGES / 64, 256, G_SIZE>>>(0, an, dist, ei, b0, g0, be0);
    k_hist     <<<E_EDGES / 256, 256>>>(ei);
    k_scan     <<<1, 1024>>>();
    k_scatter  <<<E_EDGES / 256, 256>>>(ei);
    k_mlp<<<E_EDGES / 64, 256, G_SIZE>>>(1, an, dist, ei, b1, g1, be1);
    k_out<<<dim3(2, E_EDGES / 64), 256, H_SIZE>>>(b2, env);
    k_wigner<<<NNODES, 320>>>(wig, out);
}

// round 7
// speedup vs baseline: 2.0931x; 1.0911x over previous
#include <cuda_runtime.h>
#include <cuda_bf16.h>
#include <cstdint>

#define E_EDGES 160000
#define NNODES  10000
#define NT_E    (E_EDGES / 16)      // 10000 edge-row tiles

// ---------------- scratch (device globals) ----------------
// activation A-fragments: [rowTile][kt(8)][lane(32)] -> uint4 (4 bf16x2 regs)
__device__ __align__(16) uint4 g_hf_hi [NT_E * 8 * 32];
__device__ __align__(16) uint4 g_hf_lo [NT_E * 8 * 32];
__device__ __align__(16) uint4 g_h2f_hi[NT_E * 8 * 32];
__device__ __align__(16) uint4 g_h2f_lo[NT_E * 8 * 32];
__device__ __align__(16) float g_y [E_EDGES * 320];
// weight B-fragments: [nt][kt(8)][lane(32)] -> uint2 (2 bf16x2 regs)
__device__ __align__(16) uint2 W0f_hi[16 * 8 * 32], W0f_lo[16 * 8 * 32];
__device__ __align__(16) uint2 W1f_hi[16 * 8 * 32], W1f_lo[16 * 8 * 32];
__device__ __align__(16) uint2 W2f_hi[40 * 8 * 32], W2f_lo[40 * 8 * 32];
// precomputed embedding projections (fp32 exact)
__device__ __align__(16) float g_Psrc[90 * 128];
__device__ __align__(16) float g_Ptgt[90 * 128];
__device__ int g_hist [NNODES];
__device__ int g_off  [NNODES + 1];
__device__ int g_cur  [NNODES];
__device__ int g_order[E_EDGES];

// ---------------- helpers ----------------
__device__ __forceinline__ uint32_t smem_u32(const void* p) {
    uint32_t a;
    asm("{ .reg .u64 t; cvta.to.shared.u64 t, %1; cvt.u32.u64 %0, t; }" : "=r"(a) : "l"(p));
    return a;
}
__device__ __forceinline__ void ldm4(uint32_t* r, uint32_t addr) {
    asm volatile("ldmatrix.sync.aligned.m8n8.x4.shared.b16 {%0,%1,%2,%3}, [%4];"
                 : "=r"(r[0]), "=r"(r[1]), "=r"(r[2]), "=r"(r[3]) : "r"(addr));
}
__device__ __forceinline__ void mma_bf16(float* c, const uint32_t* a, const uint32_t* b) {
    asm volatile(
        "mma.sync.aligned.m16n8k16.row.col.f32.bf16.bf16.f32 "
        "{%0,%1,%2,%3}, {%4,%5,%6,%7}, {%8,%9}, {%0,%1,%2,%3};"
        : "+f"(c[0]), "+f"(c[1]), "+f"(c[2]), "+f"(c[3])
        : "r"(a[0]), "r"(a[1]), "r"(a[2]), "r"(a[3]), "r"(b[0]), "r"(b[1]));
}
__device__ __forceinline__ float silu(float x) { return x / (1.0f + __expf(-x)); }
__device__ __forceinline__ unsigned short bf_bits(__nv_bfloat16 h) {
    return *reinterpret_cast<unsigned short*>(&h);
}
__device__ __forceinline__ void split2pack(float x0, float x1, uint32_t& hw, uint32_t& lw) {
    __nv_bfloat16 h0 = __float2bfloat16(x0), h1 = __float2bfloat16(x1);
    __nv_bfloat16 l0 = __float2bfloat16(x0 - __bfloat162float(h0));
    __nv_bfloat16 l1 = __float2bfloat16(x1 - __bfloat162float(h1));
    hw = (uint32_t)bf_bits(h0) | ((uint32_t)bf_bits(h1) << 16);
    lw = (uint32_t)bf_bits(l0) | ((uint32_t)bf_bits(l1) << 16);
}
__device__ __forceinline__ void split8(const float* f, uint4& hq, uint4& lq) {
    __nv_bfloat16* hp = (__nv_bfloat16*)&hq;
    __nv_bfloat16* lp = (__nv_bfloat16*)&lq;
#pragma unroll
    for (int j = 0; j < 8; j++) {
        __nv_bfloat16 h = __float2bfloat16(f[j]);
        hp[j] = h;
        lp[j] = __float2bfloat16(f[j] - __bfloat162float(h));
    }
}

// ============================================================================
// k_prep: weights -> B-fragment layout, bf16 hi/lo split.
// frag value: reg r = pack(W[k0+2q+8r][n], W[k0+2q+1+8r][n]), n = nt*8+g.
// ============================================================================
__global__ __launch_bounds__(256) void k_prep(
    const float* __restrict__ w0, const float* __restrict__ w1,
    const float* __restrict__ w2)
{
    int idx = blockIdx.x * 256 + threadIdx.x;
    const float* W; int ld; uint2 *H, *L; int base;
    if (idx < 4096)       { W = w0; ld = 128; H = W0f_hi; L = W0f_lo; base = idx; }
    else if (idx < 8192)  { W = w1; ld = 128; H = W1f_hi; L = W1f_lo; base = idx - 4096; }
    else if (idx < 18432) { W = w2; ld = 320; H = W2f_hi; L = W2f_lo; base = idx - 8192; }
    else return;
    int lane = base & 31, kt = (base >> 5) & 7, nt = base >> 8;
    int g = lane >> 2, q = lane & 3, n = nt * 8 + g;
    uint2 hv, lv;
    { int k = kt * 16 + 2 * q;     split2pack(W[(size_t)k * ld + n], W[(size_t)(k + 1) * ld + n], hv.x, lv.x); }
    { int k = kt * 16 + 2 * q + 8; split2pack(W[(size_t)k * ld + n], W[(size_t)(k + 1) * ld + n], hv.y, lv.y); }
    H[base] = hv; L[base] = lv;
}

// ============================================================================
// k_pemb: P_src[z][n] = sum_k semb[z][k] * w0[128+k][n]  (fp32, 180 blocks)
// ============================================================================
__global__ __launch_bounds__(128) void k_pemb(
    const float* __restrict__ semb, const float* __restrict__ temb,
    const float* __restrict__ w0)
{
    __shared__ float er[128];
    const int bx = blockIdx.x;
    const int z = (bx < 90) ? bx : bx - 90;
    const int tid = threadIdx.x;
    const float* emb = (bx < 90) ? semb : temb;
    const int off = (bx < 90) ? 128 : 256;
    er[tid] = emb[z * 128 + tid];
    __syncthreads();
    float s = 0.f;
#pragma unroll 8
    for (int k = 0; k < 128; k++)
        s += er[k] * w0[(size_t)(off + k) * 128 + tid];
    float* P = (bx < 90) ? g_Psrc : g_Ptgt;
    P[z * 128 + tid] = s;
}

// ============================================================================
// k_mlp<LAYER>: [64 x 128] x [128 x 128] HMMA bf16x3 + bias (+P) + LN + SiLU.
// 256 threads, 8 warps 2x4, warp tile 32x32.
// LAYER 0: A from dist via one-shot smem stage + ldmatrix; B direct frag LDG.
// LAYER 1: A direct frag LDG from g_hf; B direct frag LDG. No mainloop smem.
// Output written in A-fragment layout for the next consumer.
// ============================================================================
template<int LAYER>
__global__ __launch_bounds__(256, 2) void k_mlp(
    const int* __restrict__ an, const float* __restrict__ dist,
    const int* __restrict__ ei,
    const float* __restrict__ bias, const float* __restrict__ gamma,
    const float* __restrict__ betap)
{
    constexpr int ASZ = (LAYER == 0) ? 34816 : 16;   // 2 x 64*272 (hi/lo)
    __shared__ __align__(16) unsigned char smA[ASZ];
    __shared__ float redS[256], redQ[256];
    __shared__ float sbias[128], sgam[128], sbet[128];
    __shared__ int szs[64], szt[64];

    const int tid = threadIdx.x;
    const int wid = tid >> 5, lane = tid & 31;
    const int gid = lane >> 2, qid = lane & 3;
    const int wid_m = wid >> 2, wid_n = wid & 3;
    const int warpRow = wid_m * 32, warpCol = wid_n * 32;
    const int e0 = blockIdx.x * 64;

    if (tid < 128) { sbias[tid] = bias[tid]; sgam[tid] = gamma[tid]; sbet[tid] = betap[tid]; }
    if (LAYER == 0 && tid < 64) {
        szs[tid] = an[ei[e0 + tid]];
        szt[tid] = an[ei[E_EDGES + e0 + tid]];
    }

    if (LAYER == 0) {
        // stage dist 64x128 fp32 -> bf16 hi/lo smem (row stride 272B: conflict-free ldmatrix)
        int row = tid >> 2, c0 = (tid & 3) * 32;
        const float* sp = dist + (size_t)(e0 + row) * 128 + c0;
#pragma unroll
        for (int q4 = 0; q4 < 4; q4++) {
            float f[8];
            float4 x0 = ((const float4*)sp)[q4 * 2];
            float4 x1 = ((const float4*)sp)[q4 * 2 + 1];
            f[0] = x0.x; f[1] = x0.y; f[2] = x0.z; f[3] = x0.w;
            f[4] = x1.x; f[5] = x1.y; f[6] = x1.z; f[7] = x1.w;
            uint4 hq, lq;
            split8(f, hq, lq);
            uint32_t off = row * 272 + c0 * 2 + q4 * 16;
            *(uint4*)(smA + off)         = hq;
            *(uint4*)(smA + 17408 + off) = lq;
        }
    }
    __syncthreads();

    float acc[2][4][4];
#pragma unroll
    for (int i = 0; i < 2; i++)
#pragma unroll
        for (int j = 0; j < 4; j++)
#pragma unroll
            for (int c = 0; c < 4; c++) acc[i][j][c] = 0.f;

    const uint2* __restrict__ Bh = (LAYER == 0) ? W0f_hi : W1f_hi;
    const uint2* __restrict__ Bl = (LAYER == 0) ? W0f_lo : W1f_lo;
    const uint32_t sbA = smem_u32(smA);
    const int Rbase = (e0 >> 4) + wid_m * 2;

#pragma unroll
    for (int kt = 0; kt < 8; kt++) {
        uint32_t a_hi[2][4], a_lo[2][4];
        if (LAYER == 0) {
            const int rA = ((lane >> 3) & 1) * 8 + (lane & 7);
            const int cA = kt * 16 + (lane >> 4) * 8;
#pragma unroll
            for (int i = 0; i < 2; i++) {
                uint32_t ad = sbA + (warpRow + i * 16 + rA) * 272 + cA * 2;
                ldm4(a_hi[i], ad);
                ldm4(a_lo[i], ad + 17408);
            }
        } else {
#pragma unroll
            for (int i = 0; i < 2; i++) {
                int fi = ((Rbase + i) * 8 + kt) * 32 + lane;
                uint4 h4 = g_hf_hi[fi];
                a_hi[i][0] = h4.x; a_hi[i][1] = h4.y; a_hi[i][2] = h4.z; a_hi[i][3] = h4.w;
                uint4 l4 = g_hf_lo[fi];
                a_lo[i][0] = l4.x; a_lo[i][1] = l4.y; a_lo[i][2] = l4.z; a_lo[i][3] = l4.w;
            }
        }
        uint32_t b_hi[4][2], b_lo[4][2];
#pragma unroll
        for (int j = 0; j < 4; j++) {
            int fi = ((wid_n * 4 + j) * 8 + kt) * 32 + lane;
            uint2 h2 = Bh[fi]; b_hi[j][0] = h2.x; b_hi[j][1] = h2.y;
            uint2 l2 = Bl[fi]; b_lo[j][0] = l2.x; b_lo[j][1] = l2.y;
        }
#pragma unroll
        for (int i = 0; i < 2; i++)
#pragma unroll
            for (int j = 0; j < 4; j++) {
                mma_bf16(acc[i][j], a_hi[i], b_hi[j]);
                mma_bf16(acc[i][j], a_hi[i], b_lo[j]);
                mma_bf16(acc[i][j], a_lo[i], b_hi[j]);
            }
    }

    // ---- epilogue pass 1: +bias (+P), partial LN sums ----
#pragma unroll
    for (int i = 0; i < 2; i++)
#pragma unroll
        for (int h = 0; h < 2; h++) {
            int row = warpRow + i * 16 + h * 8 + gid;
            const float* ps = (LAYER == 0) ? (g_Psrc + (size_t)szs[row] * 128) : nullptr;
            const float* pt = (LAYER == 0) ? (g_Ptgt + (size_t)szt[row] * 128) : nullptr;
            float s = 0.f, q = 0.f;
#pragma unroll
            for (int j = 0; j < 4; j++) {
                int col = warpCol + j * 8 + qid * 2;
                float v0 = acc[i][j][2 * h]     + sbias[col];
                float v1 = acc[i][j][2 * h + 1] + sbias[col + 1];
                if (LAYER == 0) {
                    float2 a = *(const float2*)(ps + col);
                    float2 b = *(const float2*)(pt + col);
                    v0 += a.x + b.x; v1 += a.y + b.y;
                }
                acc[i][j][2 * h] = v0; acc[i][j][2 * h + 1] = v1;
                s += v0 + v1; q += v0 * v0 + v1 * v1;
            }
            s += __shfl_xor_sync(0xffffffffu, s, 1);
            s += __shfl_xor_sync(0xffffffffu, s, 2);
            q += __shfl_xor_sync(0xffffffffu, q, 1);
            q += __shfl_xor_sync(0xffffffffu, q, 2);
            if (qid == 0) { redS[row * 4 + wid_n] = s; redQ[row * 4 + wid_n] = q; }
        }
    __syncthreads();

    // ---- epilogue pass 2: LN + SiLU + split, store A-fragment layout ----
    uint4* __restrict__ Oh = (LAYER == 0) ? g_hf_hi : g_h2f_hi;
    uint4* __restrict__ Ol = (LAYER == 0) ? g_hf_lo : g_h2f_lo;
#pragma unroll
    for (int i = 0; i < 2; i++) {
        uint4 vh[2], vl[2];
#pragma unroll
        for (int h = 0; h < 2; h++) {
            int row = warpRow + i * 16 + h * 8 + gid;
            float st = redS[row * 4] + redS[row * 4 + 1] + redS[row * 4 + 2] + redS[row * 4 + 3];
            float qt = redQ[row * 4] + redQ[row * 4 + 1] + redQ[row * 4 + 2] + redQ[row * 4 + 3];
            float mu   = st * (1.0f / 128.0f);
            float var  = qt * (1.0f / 128.0f) - mu * mu;
            float rinv = rsqrtf(var + 1e-5f);
#pragma unroll
            for (int j = 0; j < 4; j++) {
                int col = warpCol + j * 8 + qid * 2;
                float y0 = silu((acc[i][j][2 * h]     - mu) * rinv * sgam[col]     + sbet[col]);
                float y1 = silu((acc[i][j][2 * h + 1] - mu) * rinv * sgam[col + 1] + sbet[col + 1]);
                uint32_t hw, lw;
                split2pack(y0, y1, hw, lw);
                int r = h + 2 * (j & 1), jp = j >> 1;
                (&vh[jp].x)[r] = hw;
                (&vl[jp].x)[r] = lw;
            }
        }
#pragma unroll
        for (int jp = 0; jp < 2; jp++) {
            int kt2 = wid_n * 2 + jp;
            int fi = ((Rbase + i) * 8 + kt2) * 32 + lane;
            Oh[fi] = vh[jp];
            Ol[fi] = vl[jp];
        }
    }
}

// ============================================================================
// k_out: [64 x 128] x [128 x 160] HMMA bf16x3, +b2, *env*0.2 -> g_y (row-major)
// grid (2, 2500); A/B both direct fragment LDG; no mainloop smem.
// ============================================================================
__global__ __launch_bounds__(256, 2) void k_out(
    const float* __restrict__ bias, const float* __restrict__ env)
{
    __shared__ float hbias[160], henv[64];
    const int tid = threadIdx.x;
    const int wid = tid >> 5, lane = tid & 31;
    const int gid = lane >> 2, qid = lane & 3;
    const int wid_m = wid >> 2, wid_n = wid & 3;
    const int warpRow = wid_m * 32, warpCol = wid_n * 40;
    const int e0 = blockIdx.y * 64;
    const int n0 = blockIdx.x * 160;

    if (tid < 160) hbias[tid] = bias[n0 + tid];
    if (tid < 64)  henv[tid] = env[e0 + tid] * 0.2f;
    __syncthreads();

    float acc[2][5][4];
#pragma unroll
    for (int i = 0; i < 2; i++)
#pragma unroll
        for (int j = 0; j < 5; j++)
#pragma unroll
            for (int c = 0; c < 4; c++) acc[i][j][c] = 0.f;

    const int Rbase = (e0 >> 4) + wid_m * 2;
    const int ntBase = (n0 >> 3) + wid_n * 5;

#pragma unroll
    for (int kt = 0; kt < 8; kt++) {
        uint32_t a_hi[2][4], a_lo[2][4];
#pragma unroll
        for (int i = 0; i < 2; i++) {
            int fi = ((Rbase + i) * 8 + kt) * 32 + lane;
            uint4 h4 = g_h2f_hi[fi];
            a_hi[i][0] = h4.x; a_hi[i][1] = h4.y; a_hi[i][2] = h4.z; a_hi[i][3] = h4.w;
            uint4 l4 = g_h2f_lo[fi];
            a_lo[i][0] = l4.x; a_lo[i][1] = l4.y; a_lo[i][2] = l4.z; a_lo[i][3] = l4.w;
        }
        uint32_t b_hi[5][2], b_lo[5][2];
#pragma unroll
        for (int j = 0; j < 5; j++) {
            int fi = ((ntBase + j) * 8 + kt) * 32 + lane;
            uint2 h2 = W2f_hi[fi]; b_hi[j][0] = h2.x; b_hi[j][1] = h2.y;
            uint2 l2 = W2f_lo[fi]; b_lo[j][0] = l2.x; b_lo[j][1] = l2.y;
        }
#pragma unroll
        for (int i = 0; i < 2; i++)
#pragma unroll
            for (int j = 0; j < 5; j++) {
                mma_bf16(acc[i][j], a_hi[i], b_hi[j]);
                mma_bf16(acc[i][j], a_hi[i], b_lo[j]);
                mma_bf16(acc[i][j], a_lo[i], b_hi[j]);
            }
    }

#pragma unroll
    for (int i = 0; i < 2; i++)
#pragma unroll
        for (int h = 0; h < 2; h++) {
            int row = warpRow + i * 16 + h * 8 + gid;
            float es = henv[row];
            float* yp = g_y + (size_t)(e0 + row) * 320 + n0;
#pragma unroll
            for (int j = 0; j < 5; j++) {
                int col = warpCol + j * 8 + qid * 2;
                float2 o;
                o.x = (acc[i][j][2 * h]     + hbias[col])     * es;
                o.y = (acc[i][j][2 * h + 1] + hbias[col + 1]) * es;
                *(float2*)(yp + col) = o;
            }
        }
}

// ============================================================================
// counting sort by target node
// ============================================================================
__global__ void k_zero_hist() {
    int i = blockIdx.x * blockDim.x + threadIdx.x;
    if (i < NNODES) g_hist[i] = 0;
}
__global__ void k_hist(const int* __restrict__ ei) {
    int e = blockIdx.x * blockDim.x + threadIdx.x;
    if (e < E_EDGES) atomicAdd(&g_hist[ei[E_EDGES + e]], 1);
}
__global__ __launch_bounds__(1024) void k_scan() {
    __shared__ int part[1024];
    const int tid = threadIdx.x;
    const int base = tid * 10;
    int local[10];
    int s = 0;
#pragma unroll
    for (int j = 0; j < 10; j++) {
        int idx = base + j;
        int h = (idx < NNODES) ? g_hist[idx] : 0;
        local[j] = s; s += h;
    }
    part[tid] = s;
    __syncthreads();
    for (int o = 1; o < 1024; o <<= 1) {
        int v = 0;
        if (tid >= o) v = part[tid - o];
        __syncthreads();
        part[tid] += v;
        __syncthreads();
    }
    int prev = (tid == 0) ? 0 : part[tid - 1];
#pragma unroll
    for (int j = 0; j < 10; j++) {
        int idx = base + j;
        if (idx < NNODES) { g_off[idx] = prev + local[j]; g_cur[idx] = prev + local[j]; }
    }
    if (tid == 1023) g_off[NNODES] = prev + s;
}
__global__ void k_scatter(const int* __restrict__ ei) {
    int e = blockIdx.x * blockDim.x + threadIdx.x;
    if (e < E_EDGES) {
        int t = ei[E_EDGES + e];
        int p = atomicAdd(&g_cur[t], 1);
        g_order[p] = e;
    }
}

// ============================================================================
// k_wigner: per-node rotate + segment sum. 320 threads; register accumulators.
// ============================================================================
#define WB 8
__global__ __launch_bounds__(320) void k_wigner(
    const float* __restrict__ wig, float* __restrict__ out)
{
    const int node = blockIdx.x;
    const int tid  = threadIdx.x;
    const int c = tid & 63, mg = tid >> 6;
    __shared__ __align__(16) float ys[WB * 320];
    __shared__ float sw[WB * 128];

    float acc[5] = {0.f, 0.f, 0.f, 0.f, 0.f};
    const int beg = g_off[node];
    const int end = g_off[node + 1];

    for (int p = beg; p < end; p += WB) {
        const int nb = min(WB, end - p);
        __syncthreads();
#pragma unroll
        for (int r = 0; r < 2; r++) {
            int v = tid + r * 320;
            int j = v / 80, idx = v - j * 80;
            if (j < nb) {
                int e = g_order[p + j];
                ((float4*)ys)[j * 80 + idx] =
                    ((const float4*)(g_y + (size_t)e * 320))[idx];
            }
        }
        if (tid < 200) {
            int j = tid / 25, m = tid - j * 25;
            if (j < nb) {
                int e = g_order[p + j];
                const float* wp = wig + (size_t)e * 625 + m * 25;
                float* dp = sw + j * 128 + m * 5;
                dp[0] = wp[0]; dp[1] = wp[1]; dp[2] = wp[2];
                dp[3] = wp[3]; dp[4] = wp[4];
            }
        }
        __syncthreads();
        for (int j = 0; j < nb; j++) {
            const float* yy = ys + j * 320;
            float y0 = yy[c], y1 = yy[64 + c], y2 = yy[128 + c],
                  y3 = yy[192 + c], y4 = yy[256 + c];
            const float* wj = sw + j * 128 + mg * 25;
#pragma unroll
            for (int jm = 0; jm < 5; jm++) {
                const float* w = wj + jm * 5;
                acc[jm] += w[0] * y0 + w[1] * y1 + w[2] * y2 + w[3] * y3 + w[4] * y4;
            }
        }
    }
    float* op = out + (size_t)node * 1600;
#pragma unroll
    for (int jm = 0; jm < 5; jm++)
        op[(mg * 5 + jm) * 64 + c] = acc[jm];
}

// ============================================================================
extern "C" void kernel_launch(void* const* d_in, const int* in_sizes, int n_in,
                              void* d_out, int out_size)
{
    const int*   an   = (const int*)  d_in[0];
    const float* dist = (const float*)d_in[1];
    const int*   ei   = (const int*)  d_in[2];
    const float* env  = (const float*)d_in[3];
    const float* semb = (const float*)d_in[4];
    const float* temb = (const float*)d_in[5];
    const float* w0   = (const float*)d_in[6];
    const float* b0   = (const float*)d_in[7];
    const float* g0   = (const float*)d_in[8];
    const float* be0  = (const float*)d_in[9];
    const float* w1   = (const float*)d_in[10];
    const float* b1   = (const float*)d_in[11];
    const float* g1   = (const float*)d_in[12];
    const float* be1  = (const float*)d_in[13];
    const float* w2   = (const float*)d_in[14];
    const float* b2   = (const float*)d_in[15];
    const float* wig  = (const float*)d_in[16];
    float* out = (float*)d_out;

    // launch #4 gets profiled by the harness's ncu capture -> k_mlp<0> there
    k_prep     <<<72, 256>>>(w0, w1, w2);
    k_pemb     <<<180, 128>>>(semb, temb, w0);
    k_zero_hist<<<(NNODES + 255) / 256, 256>>>();
    k_mlp<0>   <<<E_EDGES / 64, 256>>>(an, dist, ei, b0, g0, be0);
    k_hist     <<<E_EDGES / 256, 256>>>(ei);
    k_scan     <<<1, 1024>>>();
    k_scatter  <<<E_EDGES / 256, 256>>>(ei);
    k_mlp<1>   <<<E_EDGES / 64, 256>>>(an, dist, ei, b1, g1, be1);
    k_out      <<<dim3(2, E_EDGES / 64), 256>>>(b2, env);
    k_wigner   <<<NNODES, 320>>>(wig, out);
}

// round 10
// speedup vs baseline: 2.0989x; 1.0028x over previous
#include <cuda_runtime.h>
#include <cuda_bf16.h>
#include <cstdint>

#define E_EDGES 160000
#define NNODES  10000
#define NT_E    (E_EDGES / 16)      // 10000 edge-row tiles

// ---------------- scratch (device globals) ----------------
// activation A-fragments: [rowTile][kt(8)][lane(32)] -> uint4 (4 bf16x2 regs)
__device__ __align__(16) uint4 g_h2f_hi[NT_E * 8 * 32];
__device__ __align__(16) uint4 g_h2f_lo[NT_E * 8 * 32];
__device__ __align__(16) float g_y [E_EDGES * 320];
// weight B-fragments: [nt][kt(8)][lane(32)] -> uint2 (2 bf16x2 regs)
__device__ __align__(16) uint2 W0f_hi[16 * 8 * 32], W0f_lo[16 * 8 * 32];
__device__ __align__(16) uint2 W1f_hi[16 * 8 * 32], W1f_lo[16 * 8 * 32];
__device__ __align__(16) uint2 W2f_hi[40 * 8 * 32], W2f_lo[40 * 8 * 32];
// precomputed embedding projections (fp32 exact)
__device__ __align__(16) float g_Psrc[90 * 128];
__device__ __align__(16) float g_Ptgt[90 * 128];
__device__ int g_hist [NNODES];
__device__ int g_off  [NNODES + 1];
__device__ int g_cur  [NNODES];
__device__ int g_order[E_EDGES];

// ---------------- helpers ----------------
__device__ __forceinline__ uint32_t smem_u32(const void* p) {
    uint32_t a;
    asm("{ .reg .u64 t; cvta.to.shared.u64 t, %1; cvt.u32.u64 %0, t; }" : "=r"(a) : "l"(p));
    return a;
}
__device__ __forceinline__ void ldm4(uint32_t* r, uint32_t addr) {
    asm volatile("ldmatrix.sync.aligned.m8n8.x4.shared.b16 {%0,%1,%2,%3}, [%4];"
                 : "=r"(r[0]), "=r"(r[1]), "=r"(r[2]), "=r"(r[3]) : "r"(addr));
}
__device__ __forceinline__ void mma_bf16(float* c, const uint32_t* a, const uint32_t* b) {
    asm volatile(
        "mma.sync.aligned.m16n8k16.row.col.f32.bf16.bf16.f32 "
        "{%0,%1,%2,%3}, {%4,%5,%6,%7}, {%8,%9}, {%0,%1,%2,%3};"
        : "+f"(c[0]), "+f"(c[1]), "+f"(c[2]), "+f"(c[3])
        : "r"(a[0]), "r"(a[1]), "r"(a[2]), "r"(a[3]), "r"(b[0]), "r"(b[1]));
}
__device__ __forceinline__ float silu(float x) { return x / (1.0f + __expf(-x)); }
__device__ __forceinline__ unsigned short bf_bits(__nv_bfloat16 h) {
    return *reinterpret_cast<unsigned short*>(&h);
}
__device__ __forceinline__ void split2pack(float x0, float x1, uint32_t& hw, uint32_t& lw) {
    __nv_bfloat16 h0 = __float2bfloat16(x0), h1 = __float2bfloat16(x1);
    __nv_bfloat16 l0 = __float2bfloat16(x0 - __bfloat162float(h0));
    __nv_bfloat16 l1 = __float2bfloat16(x1 - __bfloat162float(h1));
    hw = (uint32_t)bf_bits(h0) | ((uint32_t)bf_bits(h1) << 16);
    lw = (uint32_t)bf_bits(l0) | ((uint32_t)bf_bits(l1) << 16);
}
__device__ __forceinline__ void split8(const float* f, uint4& hq, uint4& lq) {
    __nv_bfloat16* hp = (__nv_bfloat16*)&hq;
    __nv_bfloat16* lp = (__nv_bfloat16*)&lq;
#pragma unroll
    for (int j = 0; j < 8; j++) {
        __nv_bfloat16 h = __float2bfloat16(f[j]);
        hp[j] = h;
        lp[j] = __float2bfloat16(f[j] - __bfloat162float(h));
    }
}

// ============================================================================
// k_prep: weights -> B-fragment layout, bf16 hi/lo split.
// ============================================================================
__global__ __launch_bounds__(256) void k_prep(
    const float* __restrict__ w0, const float* __restrict__ w1,
    const float* __restrict__ w2)
{
    int idx = blockIdx.x * 256 + threadIdx.x;
    const float* W; int ld; uint2 *H, *L; int base;
    if (idx < 4096)       { W = w0; ld = 128; H = W0f_hi; L = W0f_lo; base = idx; }
    else if (idx < 8192)  { W = w1; ld = 128; H = W1f_hi; L = W1f_lo; base = idx - 4096; }
    else if (idx < 18432) { W = w2; ld = 320; H = W2f_hi; L = W2f_lo; base = idx - 8192; }
    else return;
    int lane = base & 31, kt = (base >> 5) & 7, nt = base >> 8;
    int g = lane >> 2, q = lane & 3, n = nt * 8 + g;
    uint2 hv, lv;
    { int k = kt * 16 + 2 * q;     split2pack(W[(size_t)k * ld + n], W[(size_t)(k + 1) * ld + n], hv.x, lv.x); }
    { int k = kt * 16 + 2 * q + 8; split2pack(W[(size_t)k * ld + n], W[(size_t)(k + 1) * ld + n], hv.y, lv.y); }
    H[base] = hv; L[base] = lv;
}

// ============================================================================
// k_pemb: P_src[z][n] = sum_k semb[z][k] * w0[128+k][n]  (fp32, 180 blocks)
// ============================================================================
__global__ __launch_bounds__(128) void k_pemb(
    const float* __restrict__ semb, const float* __restrict__ temb,
    const float* __restrict__ w0)
{
    __shared__ float er[128];
    const int bx = blockIdx.x;
    const int z = (bx < 90) ? bx : bx - 90;
    const int tid = threadIdx.x;
    const float* emb = (bx < 90) ? semb : temb;
    const int off = (bx < 90) ? 128 : 256;
    er[tid] = emb[z * 128 + tid];
    __syncthreads();
    float s = 0.f;
#pragma unroll 8
    for (int k = 0; k < 128; k++)
        s += er[k] * w0[(size_t)(off + k) * 128 + tid];
    float* P = (bx < 90) ? g_Psrc : g_Ptgt;
    P[z * 128 + tid] = s;
}

// ============================================================================
// k_mlp01: FUSED layer0+layer1. [64 x 128]x[128 x 128] twice, bf16x3 HMMA.
// Layer0: A from dist (smem stage + ldmatrix), +bias+P, LN, SiLU
//         -> fragments handed to layer1 through SMEM (no gmem round trip).
// Layer1: A frags from smem (LDS.128), B frags LDG, +bias, LN, SiLU
//         -> g_h2f in A-fragment layout for k_out.
// 256 threads, 8 warps 2x4, warp tile 32x32.
// ============================================================================
__global__ __launch_bounds__(256, 2) void k_mlp01(
    const int* __restrict__ an, const float* __restrict__ dist,
    const int* __restrict__ ei,
    const float* __restrict__ b0, const float* __restrict__ g0,
    const float* __restrict__ be0,
    const float* __restrict__ b1, const float* __restrict__ g1,
    const float* __restrict__ be1)
{
    // smA: layer0 dist stage (34816 B) aliased with frag handoff (32768 B)
    __shared__ __align__(16) unsigned char smA[34816];
    __shared__ float redS[256], redQ[256];
    __shared__ float sb0[128], sg0[128], sbe0[128];
    __shared__ float sb1[128], sg1[128], sbe1[128];
    __shared__ int szs[64], szt[64];

    const int tid = threadIdx.x;
    const int wid = tid >> 5, lane = tid & 31;
    const int gid = lane >> 2, qid = lane & 3;
    const int wid_m = wid >> 2, wid_n = wid & 3;
    const int warpRow = wid_m * 32, warpCol = wid_n * 32;
    const int e0 = blockIdx.x * 64;

    if (tid < 128) {
        sb0[tid] = b0[tid]; sg0[tid] = g0[tid]; sbe0[tid] = be0[tid];
        sb1[tid] = b1[tid]; sg1[tid] = g1[tid]; sbe1[tid] = be1[tid];
    }
    if (tid < 64) {
        szs[tid] = an[ei[e0 + tid]];
        szt[tid] = an[ei[E_EDGES + e0 + tid]];
    }

    {   // stage dist 64x128 fp32 -> bf16 hi/lo smem (row stride 272B)
        int row = tid >> 2, c0 = (tid & 3) * 32;
        const float* sp = dist + (size_t)(e0 + row) * 128 + c0;
#pragma unroll
        for (int q4 = 0; q4 < 4; q4++) {
            float f[8];
            float4 x0 = ((const float4*)sp)[q4 * 2];
            float4 x1 = ((const float4*)sp)[q4 * 2 + 1];
            f[0] = x0.x; f[1] = x0.y; f[2] = x0.z; f[3] = x0.w;
            f[4] = x1.x; f[5] = x1.y; f[6] = x1.z; f[7] = x1.w;
            uint4 hq, lq;
            split8(f, hq, lq);
            uint32_t off = row * 272 + c0 * 2 + q4 * 16;
            *(uint4*)(smA + off)         = hq;
            *(uint4*)(smA + 17408 + off) = lq;
        }
    }
    __syncthreads();

    float acc[2][4][4];
#pragma unroll
    for (int i = 0; i < 2; i++)
#pragma unroll
        for (int j = 0; j < 4; j++)
#pragma unroll
            for (int c = 0; c < 4; c++) acc[i][j][c] = 0.f;

    const uint32_t sbA = smem_u32(smA);
    const int Rbase = (e0 >> 4) + wid_m * 2;

    // ======== LAYER 0 mainloop: A via ldmatrix, B = W0 frags (LDG) ========
#pragma unroll
    for (int kt = 0; kt < 8; kt++) {
        uint32_t a_hi[2][4], a_lo[2][4];
        const int rA = ((lane >> 3) & 1) * 8 + (lane & 7);
        const int cA = kt * 16 + (lane >> 4) * 8;
#pragma unroll
        for (int i = 0; i < 2; i++) {
            uint32_t ad = sbA + (warpRow + i * 16 + rA) * 272 + cA * 2;
            ldm4(a_hi[i], ad);
            ldm4(a_lo[i], ad + 17408);
        }
        uint32_t b_hi[4][2], b_lo[4][2];
#pragma unroll
        for (int j = 0; j < 4; j++) {
            int fi = ((wid_n * 4 + j) * 8 + kt) * 32 + lane;
            uint2 h2 = W0f_hi[fi]; b_hi[j][0] = h2.x; b_hi[j][1] = h2.y;
            uint2 l2 = W0f_lo[fi]; b_lo[j][0] = l2.x; b_lo[j][1] = l2.y;
        }
#pragma unroll
        for (int i = 0; i < 2; i++)
#pragma unroll
            for (int j = 0; j < 4; j++) {
                mma_bf16(acc[i][j], a_hi[i], b_hi[j]);
                mma_bf16(acc[i][j], a_hi[i], b_lo[j]);
                mma_bf16(acc[i][j], a_lo[i], b_hi[j]);
            }
    }

    // ---- layer0 epilogue pass 1: +bias+P, partial LN sums ----
#pragma unroll
    for (int i = 0; i < 2; i++)
#pragma unroll
        for (int h = 0; h < 2; h++) {
            int row = warpRow + i * 16 + h * 8 + gid;
            const float* ps = g_Psrc + (size_t)szs[row] * 128;
            const float* pt = g_Ptgt + (size_t)szt[row] * 128;
            float s = 0.f, q = 0.f;
#pragma unroll
            for (int j = 0; j < 4; j++) {
                int col = warpCol + j * 8 + qid * 2;
                float2 a = *(const float2*)(ps + col);
                float2 b = *(const float2*)(pt + col);
                float v0 = acc[i][j][2 * h]     + sb0[col]     + a.x + b.x;
                float v1 = acc[i][j][2 * h + 1] + sb0[col + 1] + a.y + b.y;
                acc[i][j][2 * h] = v0; acc[i][j][2 * h + 1] = v1;
                s += v0 + v1; q += v0 * v0 + v1 * v1;
            }
            s += __shfl_xor_sync(0xffffffffu, s, 1);
            s += __shfl_xor_sync(0xffffffffu, s, 2);
            q += __shfl_xor_sync(0xffffffffu, q, 1);
            q += __shfl_xor_sync(0xffffffffu, q, 2);
            if (qid == 0) { redS[row * 4 + wid_n] = s; redQ[row * 4 + wid_n] = q; }
        }
    __syncthreads();   // also guarantees all ldmatrix reads of smA are done

    // ---- layer0 epilogue pass 2: LN+SiLU+split -> frag handoff in SMEM ----
    uint4* sOh = (uint4*)smA;               // [rt(4)][kt(8)][lane(32)]
    uint4* sOl = (uint4*)(smA + 16384);
#pragma unroll
    for (int i = 0; i < 2; i++) {
        uint4 vh[2], vl[2];
#pragma unroll
        for (int h = 0; h < 2; h++) {
            int row = warpRow + i * 16 + h * 8 + gid;
            float st = redS[row * 4] + redS[row * 4 + 1] + redS[row * 4 + 2] + redS[row * 4 + 3];
            float qt = redQ[row * 4] + redQ[row * 4 + 1] + redQ[row * 4 + 2] + redQ[row * 4 + 3];
            float mu   = st * (1.0f / 128.0f);
            float var  = qt * (1.0f / 128.0f) - mu * mu;
            float rinv = rsqrtf(var + 1e-5f);
#pragma unroll
            for (int j = 0; j < 4; j++) {
                int col = warpCol + j * 8 + qid * 2;
                float y0 = silu((acc[i][j][2 * h]     - mu) * rinv * sg0[col]     + sbe0[col]);
                float y1 = silu((acc[i][j][2 * h + 1] - mu) * rinv * sg0[col + 1] + sbe0[col + 1]);
                uint32_t hw, lw;
                split2pack(y0, y1, hw, lw);
                int r = h + 2 * (j & 1), jp = j >> 1;
                (&vh[jp].x)[r] = hw;
                (&vl[jp].x)[r] = lw;
            }
        }
#pragma unroll
        for (int jp = 0; jp < 2; jp++) {
            int kt2 = wid_n * 2 + jp;
            int fi = ((wid_m * 2 + i) * 8 + kt2) * 32 + lane;
            sOh[fi] = vh[jp];
            sOl[fi] = vl[jp];
        }
    }
    __syncthreads();

    // ======== LAYER 1 mainloop: A frags from SMEM, B = W1 frags (LDG) ========
#pragma unroll
    for (int i = 0; i < 2; i++)
#pragma unroll
        for (int j = 0; j < 4; j++)
#pragma unroll
            for (int c = 0; c < 4; c++) acc[i][j][c] = 0.f;

#pragma unroll
    for (int kt = 0; kt < 8; kt++) {
        uint32_t a_hi[2][4], a_lo[2][4];
#pragma unroll
        for (int i = 0; i < 2; i++) {
            int fi = ((wid_m * 2 + i) * 8 + kt) * 32 + lane;
            uint4 h4 = sOh[fi];
            a_hi[i][0] = h4.x; a_hi[i][1] = h4.y; a_hi[i][2] = h4.z; a_hi[i][3] = h4.w;
            uint4 l4 = sOl[fi];
            a_lo[i][0] = l4.x; a_lo[i][1] = l4.y; a_lo[i][2] = l4.z; a_lo[i][3] = l4.w;
        }
        uint32_t b_hi[4][2], b_lo[4][2];
#pragma unroll
        for (int j = 0; j < 4; j++) {
            int fi = ((wid_n * 4 + j) * 8 + kt) * 32 + lane;
            uint2 h2 = W1f_hi[fi]; b_hi[j][0] = h2.x; b_hi[j][1] = h2.y;
            uint2 l2 = W1f_lo[fi]; b_lo[j][0] = l2.x; b_lo[j][1] = l2.y;
        }
#pragma unroll
        for (int i = 0; i < 2; i++)
#pragma unroll
            for (int j = 0; j < 4; j++) {
                mma_bf16(acc[i][j], a_hi[i], b_hi[j]);
                mma_bf16(acc[i][j], a_hi[i], b_lo[j]);
                mma_bf16(acc[i][j], a_lo[i], b_hi[j]);
            }
    }

    // ---- layer1 epilogue pass 1 ----
#pragma unroll
    for (int i = 0; i < 2; i++)
#pragma unroll
        for (int h = 0; h < 2; h++) {
            int row = warpRow + i * 16 + h * 8 + gid;
            float s = 0.f, q = 0.f;
#pragma unroll
            for (int j = 0; j < 4; j++) {
                int col = warpCol + j * 8 + qid * 2;
                float v0 = acc[i][j][2 * h]     + sb1[col];
                float v1 = acc[i][j][2 * h + 1] + sb1[col + 1];
                acc[i][j][2 * h] = v0; acc[i][j][2 * h + 1] = v1;
                s += v0 + v1; q += v0 * v0 + v1 * v1;
            }
            s += __shfl_xor_sync(0xffffffffu, s, 1);
            s += __shfl_xor_sync(0xffffffffu, s, 2);
            q += __shfl_xor_sync(0xffffffffu, q, 1);
            q += __shfl_xor_sync(0xffffffffu, q, 2);
            if (qid == 0) { redS[row * 4 + wid_n] = s; redQ[row * 4 + wid_n] = q; }
        }
    __syncthreads();

    // ---- layer1 epilogue pass 2: LN+SiLU+split -> g_h2f (gmem) ----
#pragma unroll
    for (int i = 0; i < 2; i++) {
        uint4 vh[2], vl[2];
#pragma unroll
        for (int h = 0; h < 2; h++) {
            int row = warpRow + i * 16 + h * 8 + gid;
            float st = redS[row * 4] + redS[row * 4 + 1] + redS[row * 4 + 2] + redS[row * 4 + 3];
            float qt = redQ[row * 4] + redQ[row * 4 + 1] + redQ[row * 4 + 2] + redQ[row * 4 + 3];
            float mu   = st * (1.0f / 128.0f);
            float var  = qt * (1.0f / 128.0f) - mu * mu;
            float rinv = rsqrtf(var + 1e-5f);
#pragma unroll
            for (int j = 0; j < 4; j++) {
                int col = warpCol + j * 8 + qid * 2;
                float y0 = silu((acc[i][j][2 * h]     - mu) * rinv * sg1[col]     + sbe1[col]);
                float y1 = silu((acc[i][j][2 * h + 1] - mu) * rinv * sg1[col + 1] + sbe1[col + 1]);
                uint32_t hw, lw;
                split2pack(y0, y1, hw, lw);
                int r = h + 2 * (j & 1), jp = j >> 1;
                (&vh[jp].x)[r] = hw;
                (&vl[jp].x)[r] = lw;
            }
        }
#pragma unroll
        for (int jp = 0; jp < 2; jp++) {
            int kt2 = wid_n * 2 + jp;
            int fi = ((Rbase + i) * 8 + kt2) * 32 + lane;
            g_h2f_hi[fi] = vh[jp];
            g_h2f_lo[fi] = vl[jp];
        }
    }
}

// ============================================================================
// k_out: [64 x 128] x [128 x 160] HMMA bf16x3, +b2, *env*0.2 -> g_y (row-major)
// grid (2, 2500); A/B both direct fragment LDG; no mainloop smem.
// ============================================================================
__global__ __launch_bounds__(256, 2) void k_out(
    const float* __restrict__ bias, const float* __restrict__ env)
{
    __shared__ float hbias[160], henv[64];
    const int tid = threadIdx.x;
    const int wid = tid >> 5, lane = tid & 31;
    const int gid = lane >> 2, qid = lane & 3;
    const int wid_m = wid >> 2, wid_n = wid & 3;
    const int warpRow = wid_m * 32, warpCol = wid_n * 40;
    const int e0 = blockIdx.y * 64;
    const int n0 = blockIdx.x * 160;

    if (tid < 160) hbias[tid] = bias[n0 + tid];
    if (tid < 64)  henv[tid] = env[e0 + tid] * 0.2f;
    __syncthreads();

    float acc[2][5][4];
#pragma unroll
    for (int i = 0; i < 2; i++)
#pragma unroll
        for (int j = 0; j < 5; j++)
#pragma unroll
            for (int c = 0; c < 4; c++) acc[i][j][c] = 0.f;

    const int Rbase = (e0 >> 4) + wid_m * 2;
    const int ntBase = (n0 >> 3) + wid_n * 5;

#pragma unroll
    for (int kt = 0; kt < 8; kt++) {
        uint32_t a_hi[2][4], a_lo[2][4];
#pragma unroll
        for (int i = 0; i < 2; i++) {
            int fi = ((Rbase + i) * 8 + kt) * 32 + lane;
            uint4 h4 = g_h2f_hi[fi];
            a_hi[i][0] = h4.x; a_hi[i][1] = h4.y; a_hi[i][2] = h4.z; a_hi[i][3] = h4.w;
            uint4 l4 = g_h2f_lo[fi];
            a_lo[i][0] = l4.x; a_lo[i][1] = l4.y; a_lo[i][2] = l4.z; a_lo[i][3] = l4.w;
        }
        uint32_t b_hi[5][2], b_lo[5][2];
#pragma unroll
        for (int j = 0; j < 5; j++) {
            int fi = ((ntBase + j) * 8 + kt) * 32 + lane;
            uint2 h2 = W2f_hi[fi]; b_hi[j][0] = h2.x; b_hi[j][1] = h2.y;
            uint2 l2 = W2f_lo[fi]; b_lo[j][0] = l2.x; b_lo[j][1] = l2.y;
        }
#pragma unroll
        for (int i = 0; i < 2; i++)
#pragma unroll
            for (int j = 0; j < 5; j++) {
                mma_bf16(acc[i][j], a_hi[i], b_hi[j]);
                mma_bf16(acc[i][j], a_hi[i], b_lo[j]);
                mma_bf16(acc[i][j], a_lo[i], b_hi[j]);
            }
    }

#pragma unroll
    for (int i = 0; i < 2; i++)
#pragma unroll
        for (int h = 0; h < 2; h++) {
            int row = warpRow + i * 16 + h * 8 + gid;
            float es = henv[row];
            float* yp = g_y + (size_t)(e0 + row) * 320 + n0;
#pragma unroll
            for (int j = 0; j < 5; j++) {
                int col = warpCol + j * 8 + qid * 2;
                float2 o;
                o.x = (acc[i][j][2 * h]     + hbias[col])     * es;
                o.y = (acc[i][j][2 * h + 1] + hbias[col + 1]) * es;
                *(float2*)(yp + col) = o;
            }
        }
}

// ============================================================================
// counting sort by target node
// ============================================================================
__global__ void k_zero_hist() {
    int i = blockIdx.x * blockDim.x + threadIdx.x;
    if (i < NNODES) g_hist[i] = 0;
}
__global__ void k_hist(const int* __restrict__ ei) {
    int e = blockIdx.x * blockDim.x + threadIdx.x;
    if (e < E_EDGES) atomicAdd(&g_hist[ei[E_EDGES + e]], 1);
}
__global__ __launch_bounds__(1024) void k_scan() {
    __shared__ int part[1024];
    const int tid = threadIdx.x;
    const int base = tid * 10;
    int local[10];
    int s = 0;
#pragma unroll
    for (int j = 0; j < 10; j++) {
        int idx = base + j;
        int h = (idx < NNODES) ? g_hist[idx] : 0;
        local[j] = s; s += h;
    }
    part[tid] = s;
    __syncthreads();
    for (int o = 1; o < 1024; o <<= 1) {
        int v = 0;
        if (tid >= o) v = part[tid - o];
        __syncthreads();
        part[tid] += v;
        __syncthreads();
    }
    int prev = (tid == 0) ? 0 : part[tid - 1];
#pragma unroll
    for (int j = 0; j < 10; j++) {
        int idx = base + j;
        if (idx < NNODES) { g_off[idx] = prev + local[j]; g_cur[idx] = prev + local[j]; }
    }
    if (tid == 1023) g_off[NNODES] = prev + s;
}
__global__ void k_scatter(const int* __restrict__ ei) {
    int e = blockIdx.x * blockDim.x + threadIdx.x;
    if (e < E_EDGES) {
        int t = ei[E_EDGES + e];
        int p = atomicAdd(&g_cur[t], 1);
        g_order[p] = e;
    }
}

// ============================================================================
// k_wigner: per-node rotate + segment sum. 320 threads; register accumulators.
// ============================================================================
#define WB 8
__global__ __launch_bounds__(320) void k_wigner(
    const float* __restrict__ wig, float* __restrict__ out)
{
    const int node = blockIdx.x;
    const int tid  = threadIdx.x;
    const int c = tid & 63, mg = tid >> 6;
    __shared__ __align__(16) float ys[WB * 320];
    __shared__ float sw[WB * 128];

    float acc[5] = {0.f, 0.f, 0.f, 0.f, 0.f};
    const int beg = g_off[node];
    const int end = g_off[node + 1];

    for (int p = beg; p < end; p += WB) {
        const int nb = min(WB, end - p);
        __syncthreads();
#pragma unroll
        for (int r = 0; r < 2; r++) {
            int v = tid + r * 320;
            int j = v / 80, idx = v - j * 80;
            if (j < nb) {
                int e = g_order[p + j];
                ((float4*)ys)[j * 80 + idx] =
                    ((const float4*)(g_y + (size_t)e * 320))[idx];
            }
        }
        if (tid < 200) {
            int j = tid / 25, m = tid - j * 25;
            if (j < nb) {
                int e = g_order[p + j];
                const float* wp = wig + (size_t)e * 625 + m * 25;
                float* dp = sw + j * 128 + m * 5;
                dp[0] = wp[0]; dp[1] = wp[1]; dp[2] = wp[2];
                dp[3] = wp[3]; dp[4] = wp[4];
            }
        }
        __syncthreads();
        for (int j = 0; j < nb; j++) {
            const float* yy = ys + j * 320;
            float y0 = yy[c], y1 = yy[64 + c], y2 = yy[128 + c],
                  y3 = yy[192 + c], y4 = yy[256 + c];
            const float* wj = sw + j * 128 + mg * 25;
#pragma unroll
            for (int jm = 0; jm < 5; jm++) {
                const float* w = wj + jm * 5;
                acc[jm] += w[0] * y0 + w[1] * y1 + w[2] * y2 + w[3] * y3 + w[4] * y4;
            }
        }
    }
    float* op = out + (size_t)node * 1600;
#pragma unroll
    for (int jm = 0; jm < 5; jm++)
        op[(mg * 5 + jm) * 64 + c] = acc[jm];
}

// ============================================================================
extern "C" void kernel_launch(void* const* d_in, const int* in_sizes, int n_in,
                              void* d_out, int out_size)
{
    const int*   an   = (const int*)  d_in[0];
    const float* dist = (const float*)d_in[1];
    const int*   ei   = (const int*)  d_in[2];
    const float* env  = (const float*)d_in[3];
    const float* semb = (const float*)d_in[4];
    const float* temb = (const float*)d_in[5];
    const float* w0   = (const float*)d_in[6];
    const float* b0   = (const float*)d_in[7];
    const float* g0   = (const float*)d_in[8];
    const float* be0  = (const float*)d_in[9];
    const float* w1   = (const float*)d_in[10];
    const float* b1   = (const float*)d_in[11];
    const float* g1   = (const float*)d_in[12];
    const float* be1  = (const float*)d_in[13];
    const float* w2   = (const float*)d_in[14];
    const float* b2   = (const float*)d_in[15];
    const float* wig  = (const float*)d_in[16];
    float* out = (float*)d_out;

    // launch #4 gets profiled by the harness's ncu capture -> k_mlp01 there
    k_prep     <<<72, 256>>>(w0, w1, w2);
    k_pemb     <<<180, 128>>>(semb, temb, w0);
    k_zero_hist<<<(NNODES + 255) / 256, 256>>>();
    k_mlp01    <<<E_EDGES / 64, 256>>>(an, dist, ei, b0, g0, be0, b1, g1, be1);
    k_hist     <<<E_EDGES / 256, 256>>>(ei);
    k_scan     <<<1, 1024>>>();
    k_scatter  <<<E_EDGES / 256, 256>>>(ei);
    k_out      <<<dim3(2, E_EDGES / 64), 256>>>(b2, env);
    k_wigner   <<<NNODES, 320>>>(wig, out);
}

// round 11
// speedup vs baseline: 2.3275x; 1.1089x over previous
#include <cuda_runtime.h>
#include <cuda_bf16.h>
#include <cstdint>

#define E_EDGES 160000
#define NNODES  10000

// ---------------- scratch (device globals) ----------------
__device__ __align__(16) float g_y [E_EDGES * 320];
// weight B-fragments: [nt][kt(8)][lane(32)] -> uint2 (2 bf16x2 regs)
__device__ __align__(16) uint2 W0f_hi[16 * 8 * 32], W0f_lo[16 * 8 * 32];
__device__ __align__(16) uint2 W1f_hi[16 * 8 * 32], W1f_lo[16 * 8 * 32];
__device__ __align__(16) uint2 W2f_hi[40 * 8 * 32], W2f_lo[40 * 8 * 32];
// precomputed embedding projections (fp32 exact)
__device__ __align__(16) float g_Psrc[90 * 128];
__device__ __align__(16) float g_Ptgt[90 * 128];
__device__ int g_hist [NNODES];
__device__ int g_off  [NNODES + 1];
__device__ int g_cur  [NNODES];
__device__ int g_order[E_EDGES];

// ---------------- helpers ----------------
__device__ __forceinline__ uint32_t smem_u32(const void* p) {
    uint32_t a;
    asm("{ .reg .u64 t; cvta.to.shared.u64 t, %1; cvt.u32.u64 %0, t; }" : "=r"(a) : "l"(p));
    return a;
}
__device__ __forceinline__ void ldm4(uint32_t* r, uint32_t addr) {
    asm volatile("ldmatrix.sync.aligned.m8n8.x4.shared.b16 {%0,%1,%2,%3}, [%4];"
                 : "=r"(r[0]), "=r"(r[1]), "=r"(r[2]), "=r"(r[3]) : "r"(addr));
}
__device__ __forceinline__ void mma_bf16(float* c, const uint32_t* a, const uint32_t* b) {
    asm volatile(
        "mma.sync.aligned.m16n8k16.row.col.f32.bf16.bf16.f32 "
        "{%0,%1,%2,%3}, {%4,%5,%6,%7}, {%8,%9}, {%0,%1,%2,%3};"
        : "+f"(c[0]), "+f"(c[1]), "+f"(c[2]), "+f"(c[3])
        : "r"(a[0]), "r"(a[1]), "r"(a[2]), "r"(a[3]), "r"(b[0]), "r"(b[1]));
}
__device__ __forceinline__ float silu(float x) { return x / (1.0f + __expf(-x)); }
__device__ __forceinline__ unsigned short bf_bits(__nv_bfloat16 h) {
    return *reinterpret_cast<unsigned short*>(&h);
}
__device__ __forceinline__ void split2pack(float x0, float x1, uint32_t& hw, uint32_t& lw) {
    __nv_bfloat16 h0 = __float2bfloat16(x0), h1 = __float2bfloat16(x1);
    __nv_bfloat16 l0 = __float2bfloat16(x0 - __bfloat162float(h0));
    __nv_bfloat16 l1 = __float2bfloat16(x1 - __bfloat162float(h1));
    hw = (uint32_t)bf_bits(h0) | ((uint32_t)bf_bits(h1) << 16);
    lw = (uint32_t)bf_bits(l0) | ((uint32_t)bf_bits(l1) << 16);
}
__device__ __forceinline__ void split8(const float* f, uint4& hq, uint4& lq) {
    __nv_bfloat16* hp = (__nv_bfloat16*)&hq;
    __nv_bfloat16* lp = (__nv_bfloat16*)&lq;
#pragma unroll
    for (int j = 0; j < 8; j++) {
        __nv_bfloat16 h = __float2bfloat16(f[j]);
        hp[j] = h;
        lp[j] = __float2bfloat16(f[j] - __bfloat162float(h));
    }
}

// ============================================================================
// k_prep: weights -> B-fragment layout, bf16 hi/lo split.
// ============================================================================
__global__ __launch_bounds__(256) void k_prep(
    const float* __restrict__ w0, const float* __restrict__ w1,
    const float* __restrict__ w2)
{
    int idx = blockIdx.x * 256 + threadIdx.x;
    const float* W; int ld; uint2 *H, *L; int base;
    if (idx < 4096)       { W = w0; ld = 128; H = W0f_hi; L = W0f_lo; base = idx; }
    else if (idx < 8192)  { W = w1; ld = 128; H = W1f_hi; L = W1f_lo; base = idx - 4096; }
    else if (idx < 18432) { W = w2; ld = 320; H = W2f_hi; L = W2f_lo; base = idx - 8192; }
    else return;
    int lane = base & 31, kt = (base >> 5) & 7, nt = base >> 8;
    int g = lane >> 2, q = lane & 3, n = nt * 8 + g;
    uint2 hv, lv;
    { int k = kt * 16 + 2 * q;     split2pack(W[(size_t)k * ld + n], W[(size_t)(k + 1) * ld + n], hv.x, lv.x); }
    { int k = kt * 16 + 2 * q + 8; split2pack(W[(size_t)k * ld + n], W[(size_t)(k + 1) * ld + n], hv.y, lv.y); }
    H[base] = hv; L[base] = lv;
}

// ============================================================================
// k_pemb: P_src[z][n] = sum_k semb[z][k] * w0[128+k][n]  (fp32, 180 blocks)
// ============================================================================
__global__ __launch_bounds__(128) void k_pemb(
    const float* __restrict__ semb, const float* __restrict__ temb,
    const float* __restrict__ w0)
{
    __shared__ float er[128];
    const int bx = blockIdx.x;
    const int z = (bx < 90) ? bx : bx - 90;
    const int tid = threadIdx.x;
    const float* emb = (bx < 90) ? semb : temb;
    const int off = (bx < 90) ? 128 : 256;
    er[tid] = emb[z * 128 + tid];
    __syncthreads();
    float s = 0.f;
#pragma unroll 8
    for (int k = 0; k < 128; k++)
        s += er[k] * w0[(size_t)(off + k) * 128 + tid];
    float* P = (bx < 90) ? g_Psrc : g_Ptgt;
    P[z * 128 + tid] = s;
}

// ============================================================================
// k_mlp012: FULLY FUSED MLP. layer0 -> layer1 -> layer2, all bf16x3 HMMA,
// activations handed between layers through SMEM fragments. Output = g_y.
// 256 threads, 8 warps 2x4; warp tile 32x32 (L0/L1), 32x40 x2 halves (L2).
// ============================================================================
__global__ __launch_bounds__(256, 2) void k_mlp012(
    const int* __restrict__ an, const float* __restrict__ dist,
    const int* __restrict__ ei,
    const float* __restrict__ b0, const float* __restrict__ g0,
    const float* __restrict__ be0,
    const float* __restrict__ b1, const float* __restrict__ g1,
    const float* __restrict__ be1,
    const float* __restrict__ b2, const float* __restrict__ env)
{
    // smA: layer0 dist stage (34816 B) aliased with frag handoff (32768 B)
    __shared__ __align__(16) unsigned char smA[34816];
    __shared__ float redS[256], redQ[256];
    __shared__ float sb0[128], sg0[128], sbe0[128];
    __shared__ float sb1[128], sg1[128], sbe1[128];
    __shared__ float sb2[320], henv[64];
    __shared__ int szs[64], szt[64];

    const int tid = threadIdx.x;
    const int wid = tid >> 5, lane = tid & 31;
    const int gid = lane >> 2, qid = lane & 3;
    const int wid_m = wid >> 2, wid_n = wid & 3;
    const int warpRow = wid_m * 32, warpCol = wid_n * 32;
    const int e0 = blockIdx.x * 64;

    if (tid < 128) {
        sb0[tid] = b0[tid]; sg0[tid] = g0[tid]; sbe0[tid] = be0[tid];
        sb1[tid] = b1[tid]; sg1[tid] = g1[tid]; sbe1[tid] = be1[tid];
    }
    for (int i = tid; i < 320; i += 256) sb2[i] = b2[i];
    if (tid < 64) {
        szs[tid] = an[ei[e0 + tid]];
        szt[tid] = an[ei[E_EDGES + e0 + tid]];
        henv[tid] = env[e0 + tid] * 0.2f;
    }

    {   // stage dist 64x128 fp32 -> bf16 hi/lo smem (row stride 272B)
        int row = tid >> 2, c0 = (tid & 3) * 32;
        const float* sp = dist + (size_t)(e0 + row) * 128 + c0;
#pragma unroll
        for (int q4 = 0; q4 < 4; q4++) {
            float f[8];
            float4 x0 = ((const float4*)sp)[q4 * 2];
            float4 x1 = ((const float4*)sp)[q4 * 2 + 1];
            f[0] = x0.x; f[1] = x0.y; f[2] = x0.z; f[3] = x0.w;
            f[4] = x1.x; f[5] = x1.y; f[6] = x1.z; f[7] = x1.w;
            uint4 hq, lq;
            split8(f, hq, lq);
            uint32_t off = row * 272 + c0 * 2 + q4 * 16;
            *(uint4*)(smA + off)         = hq;
            *(uint4*)(smA + 17408 + off) = lq;
        }
    }
    __syncthreads();

    float acc[2][4][4];
#pragma unroll
    for (int i = 0; i < 2; i++)
#pragma unroll
        for (int j = 0; j < 4; j++)
#pragma unroll
            for (int c = 0; c < 4; c++) acc[i][j][c] = 0.f;

    const uint32_t sbA = smem_u32(smA);
    uint4* sOh = (uint4*)smA;               // frag handoff: [rt(4)][kt(8)][lane(32)]
    uint4* sOl = (uint4*)(smA + 16384);

    // ======== LAYER 0 mainloop: A via ldmatrix, B = W0 frags (LDG) ========
#pragma unroll
    for (int kt = 0; kt < 8; kt++) {
        uint32_t a_hi[2][4], a_lo[2][4];
        const int rA = ((lane >> 3) & 1) * 8 + (lane & 7);
        const int cA = kt * 16 + (lane >> 4) * 8;
#pragma unroll
        for (int i = 0; i < 2; i++) {
            uint32_t ad = sbA + (warpRow + i * 16 + rA) * 272 + cA * 2;
            ldm4(a_hi[i], ad);
            ldm4(a_lo[i], ad + 17408);
        }
        uint32_t b_hi[4][2], b_lo[4][2];
#pragma unroll
        for (int j = 0; j < 4; j++) {
            int fi = ((wid_n * 4 + j) * 8 + kt) * 32 + lane;
            uint2 h2 = W0f_hi[fi]; b_hi[j][0] = h2.x; b_hi[j][1] = h2.y;
            uint2 l2 = W0f_lo[fi]; b_lo[j][0] = l2.x; b_lo[j][1] = l2.y;
        }
#pragma unroll
        for (int i = 0; i < 2; i++)
#pragma unroll
            for (int j = 0; j < 4; j++) {
                mma_bf16(acc[i][j], a_hi[i], b_hi[j]);
                mma_bf16(acc[i][j], a_hi[i], b_lo[j]);
                mma_bf16(acc[i][j], a_lo[i], b_hi[j]);
            }
    }

    // ---- layer0 epilogue pass 1: +bias+P, partial LN sums ----
#pragma unroll
    for (int i = 0; i < 2; i++)
#pragma unroll
        for (int h = 0; h < 2; h++) {
            int row = warpRow + i * 16 + h * 8 + gid;
            const float* ps = g_Psrc + (size_t)szs[row] * 128;
            const float* pt = g_Ptgt + (size_t)szt[row] * 128;
            float s = 0.f, q = 0.f;
#pragma unroll
            for (int j = 0; j < 4; j++) {
                int col = warpCol + j * 8 + qid * 2;
                float2 a = *(const float2*)(ps + col);
                float2 b = *(const float2*)(pt + col);
                float v0 = acc[i][j][2 * h]     + sb0[col]     + a.x + b.x;
                float v1 = acc[i][j][2 * h + 1] + sb0[col + 1] + a.y + b.y;
                acc[i][j][2 * h] = v0; acc[i][j][2 * h + 1] = v1;
                s += v0 + v1; q += v0 * v0 + v1 * v1;
            }
            s += __shfl_xor_sync(0xffffffffu, s, 1);
            s += __shfl_xor_sync(0xffffffffu, s, 2);
            q += __shfl_xor_sync(0xffffffffu, q, 1);
            q += __shfl_xor_sync(0xffffffffu, q, 2);
            if (qid == 0) { redS[row * 4 + wid_n] = s; redQ[row * 4 + wid_n] = q; }
        }
    __syncthreads();   // all ldmatrix reads of smA done -> safe to overwrite

    // ---- layer0 epilogue pass 2: LN+SiLU+split -> frag handoff in SMEM ----
#pragma unroll
    for (int i = 0; i < 2; i++) {
        uint4 vh[2], vl[2];
#pragma unroll
        for (int h = 0; h < 2; h++) {
            int row = warpRow + i * 16 + h * 8 + gid;
            float st = redS[row * 4] + redS[row * 4 + 1] + redS[row * 4 + 2] + redS[row * 4 + 3];
            float qt = redQ[row * 4] + redQ[row * 4 + 1] + redQ[row * 4 + 2] + redQ[row * 4 + 3];
            float mu   = st * (1.0f / 128.0f);
            float var  = qt * (1.0f / 128.0f) - mu * mu;
            float rinv = rsqrtf(var + 1e-5f);
#pragma unroll
            for (int j = 0; j < 4; j++) {
                int col = warpCol + j * 8 + qid * 2;
                float y0 = silu((acc[i][j][2 * h]     - mu) * rinv * sg0[col]     + sbe0[col]);
                float y1 = silu((acc[i][j][2 * h + 1] - mu) * rinv * sg0[col + 1] + sbe0[col + 1]);
                uint32_t hw, lw;
                split2pack(y0, y1, hw, lw);
                int r = h + 2 * (j & 1), jp = j >> 1;
                (&vh[jp].x)[r] = hw;
                (&vl[jp].x)[r] = lw;
            }
        }
#pragma unroll
        for (int jp = 0; jp < 2; jp++) {
            int kt2 = wid_n * 2 + jp;
            int fi = ((wid_m * 2 + i) * 8 + kt2) * 32 + lane;
            sOh[fi] = vh[jp];
            sOl[fi] = vl[jp];
        }
    }
    __syncthreads();

    // ======== LAYER 1 mainloop: A frags from SMEM, B = W1 frags (LDG) ========
#pragma unroll
    for (int i = 0; i < 2; i++)
#pragma unroll
        for (int j = 0; j < 4; j++)
#pragma unroll
            for (int c = 0; c < 4; c++) acc[i][j][c] = 0.f;

#pragma unroll
    for (int kt = 0; kt < 8; kt++) {
        uint32_t a_hi[2][4], a_lo[2][4];
#pragma unroll
        for (int i = 0; i < 2; i++) {
            int fi = ((wid_m * 2 + i) * 8 + kt) * 32 + lane;
            uint4 h4 = sOh[fi];
            a_hi[i][0] = h4.x; a_hi[i][1] = h4.y; a_hi[i][2] = h4.z; a_hi[i][3] = h4.w;
            uint4 l4 = sOl[fi];
            a_lo[i][0] = l4.x; a_lo[i][1] = l4.y; a_lo[i][2] = l4.z; a_lo[i][3] = l4.w;
        }
        uint32_t b_hi[4][2], b_lo[4][2];
#pragma unroll
        for (int j = 0; j < 4; j++) {
            int fi = ((wid_n * 4 + j) * 8 + kt) * 32 + lane;
            uint2 h2 = W1f_hi[fi]; b_hi[j][0] = h2.x; b_hi[j][1] = h2.y;
            uint2 l2 = W1f_lo[fi]; b_lo[j][0] = l2.x; b_lo[j][1] = l2.y;
        }
#pragma unroll
        for (int i = 0; i < 2; i++)
#pragma unroll
            for (int j = 0; j < 4; j++) {
                mma_bf16(acc[i][j], a_hi[i], b_hi[j]);
                mma_bf16(acc[i][j], a_hi[i], b_lo[j]);
                mma_bf16(acc[i][j], a_lo[i], b_hi[j]);
            }
    }

    // ---- layer1 epilogue pass 1 ----
#pragma unroll
    for (int i = 0; i < 2; i++)
#pragma unroll
        for (int h = 0; h < 2; h++) {
            int row = warpRow + i * 16 + h * 8 + gid;
            float s = 0.f, q = 0.f;
#pragma unroll
            for (int j = 0; j < 4; j++) {
                int col = warpCol + j * 8 + qid * 2;
                float v0 = acc[i][j][2 * h]     + sb1[col];
                float v1 = acc[i][j][2 * h + 1] + sb1[col + 1];
                acc[i][j][2 * h] = v0; acc[i][j][2 * h + 1] = v1;
                s += v0 + v1; q += v0 * v0 + v1 * v1;
            }
            s += __shfl_xor_sync(0xffffffffu, s, 1);
            s += __shfl_xor_sync(0xffffffffu, s, 2);
            q += __shfl_xor_sync(0xffffffffu, q, 1);
            q += __shfl_xor_sync(0xffffffffu, q, 2);
            if (qid == 0) { redS[row * 4 + wid_n] = s; redQ[row * 4 + wid_n] = q; }
        }
    __syncthreads();   // all smem frag reads done -> safe to overwrite

    // ---- layer1 epilogue pass 2: LN+SiLU+split -> frag handoff in SMEM ----
#pragma unroll
    for (int i = 0; i < 2; i++) {
        uint4 vh[2], vl[2];
#pragma unroll
        for (int h = 0; h < 2; h++) {
            int row = warpRow + i * 16 + h * 8 + gid;
            float st = redS[row * 4] + redS[row * 4 + 1] + redS[row * 4 + 2] + redS[row * 4 + 3];
            float qt = redQ[row * 4] + redQ[row * 4 + 1] + redQ[row * 4 + 2] + redQ[row * 4 + 3];
            float mu   = st * (1.0f / 128.0f);
            float var  = qt * (1.0f / 128.0f) - mu * mu;
            float rinv = rsqrtf(var + 1e-5f);
#pragma unroll
            for (int j = 0; j < 4; j++) {
                int col = warpCol + j * 8 + qid * 2;
                float y0 = silu((acc[i][j][2 * h]     - mu) * rinv * sg1[col]     + sbe1[col]);
                float y1 = silu((acc[i][j][2 * h + 1] - mu) * rinv * sg1[col + 1] + sbe1[col + 1]);
                uint32_t hw, lw;
                split2pack(y0, y1, hw, lw);
                int r = h + 2 * (j & 1), jp = j >> 1;
                (&vh[jp].x)[r] = hw;
                (&vl[jp].x)[r] = lw;
            }
        }
#pragma unroll
        for (int jp = 0; jp < 2; jp++) {
            int kt2 = wid_n * 2 + jp;
            int fi = ((wid_m * 2 + i) * 8 + kt2) * 32 + lane;
            sOh[fi] = vh[jp];
            sOl[fi] = vl[jp];
        }
    }
    __syncthreads();

    // ======== LAYER 2: two N=160 halves; A frags from SMEM, B = W2 frags ====
#pragma unroll
    for (int nh = 0; nh < 2; nh++) {
        float acc2[2][5][4];
#pragma unroll
        for (int i = 0; i < 2; i++)
#pragma unroll
            for (int j = 0; j < 5; j++)
#pragma unroll
                for (int c = 0; c < 4; c++) acc2[i][j][c] = 0.f;

        const int ntBase = nh * 20 + wid_n * 5;
#pragma unroll
        for (int kt = 0; kt < 8; kt++) {
            uint32_t a_hi[2][4], a_lo[2][4];
#pragma unroll
            for (int i = 0; i < 2; i++) {
                int fi = ((wid_m * 2 + i) * 8 + kt) * 32 + lane;
                uint4 h4 = sOh[fi];
                a_hi[i][0] = h4.x; a_hi[i][1] = h4.y; a_hi[i][2] = h4.z; a_hi[i][3] = h4.w;
                uint4 l4 = sOl[fi];
                a_lo[i][0] = l4.x; a_lo[i][1] = l4.y; a_lo[i][2] = l4.z; a_lo[i][3] = l4.w;
            }
            uint32_t b_hi[5][2], b_lo[5][2];
#pragma unroll
            for (int j = 0; j < 5; j++) {
                int fi = ((ntBase + j) * 8 + kt) * 32 + lane;
                uint2 h2 = W2f_hi[fi]; b_hi[j][0] = h2.x; b_hi[j][1] = h2.y;
                uint2 l2 = W2f_lo[fi]; b_lo[j][0] = l2.x; b_lo[j][1] = l2.y;
            }
#pragma unroll
            for (int i = 0; i < 2; i++)
#pragma unroll
                for (int j = 0; j < 5; j++) {
                    mma_bf16(acc2[i][j], a_hi[i], b_hi[j]);
                    mma_bf16(acc2[i][j], a_hi[i], b_lo[j]);
                    mma_bf16(acc2[i][j], a_lo[i], b_hi[j]);
                }
        }

        // epilogue: +b2, *env*0.2 -> g_y
#pragma unroll
        for (int i = 0; i < 2; i++)
#pragma unroll
            for (int h = 0; h < 2; h++) {
                int row = warpRow + i * 16 + h * 8 + gid;
                float es = henv[row];
                float* yp = g_y + (size_t)(e0 + row) * 320 + nh * 160;
#pragma unroll
                for (int j = 0; j < 5; j++) {
                    int col = wid_n * 40 + j * 8 + qid * 2;
                    float2 o;
                    o.x = (acc2[i][j][2 * h]     + sb2[nh * 160 + col])     * es;
                    o.y = (acc2[i][j][2 * h + 1] + sb2[nh * 160 + col + 1]) * es;
                    *(float2*)(yp + col) = o;
                }
            }
    }
}

// ============================================================================
// counting sort by target node
// ============================================================================
__global__ void k_zero_hist() {
    int i = blockIdx.x * blockDim.x + threadIdx.x;
    if (i < NNODES) g_hist[i] = 0;
}
__global__ void k_hist(const int* __restrict__ ei) {
    int e = blockIdx.x * blockDim.x + threadIdx.x;
    if (e < E_EDGES) atomicAdd(&g_hist[ei[E_EDGES + e]], 1);
}
__global__ __launch_bounds__(1024) void k_scan() {
    __shared__ int part[1024];
    const int tid = threadIdx.x;
    const int base = tid * 10;
    int local[10];
    int s = 0;
#pragma unroll
    for (int j = 0; j < 10; j++) {
        int idx = base + j;
        int h = (idx < NNODES) ? g_hist[idx] : 0;
        local[j] = s; s += h;
    }
    part[tid] = s;
    __syncthreads();
    for (int o = 1; o < 1024; o <<= 1) {
        int v = 0;
        if (tid >= o) v = part[tid - o];
        __syncthreads();
        part[tid] += v;
        __syncthreads();
    }
    int prev = (tid == 0) ? 0 : part[tid - 1];
#pragma unroll
    for (int j = 0; j < 10; j++) {
        int idx = base + j;
        if (idx < NNODES) { g_off[idx] = prev + local[j]; g_cur[idx] = prev + local[j]; }
    }
    if (tid == 1023) g_off[NNODES] = prev + s;
}
__global__ void k_scatter(const int* __restrict__ ei) {
    int e = blockIdx.x * blockDim.x + threadIdx.x;
    if (e < E_EDGES) {
        int t = ei[E_EDGES + e];
        int p = atomicAdd(&g_cur[t], 1);
        g_order[p] = e;
    }
}

// ============================================================================
// k_wigner: per-node rotate + segment sum. 320 threads; register accumulators.
// w-tile stored at stride 8 floats -> float4-aligned loads (15 LDS/edge).
// ============================================================================
#define WB 8
__global__ __launch_bounds__(320) void k_wigner(
    const float* __restrict__ wig, float* __restrict__ out)
{
    const int node = blockIdx.x;
    const int tid  = threadIdx.x;
    const int c = tid & 63, mg = tid >> 6;
    __shared__ __align__(16) float ys[WB * 320];
    __shared__ __align__(16) float sw[WB * 256];   // [j][m*8..m*8+4]

    float acc[5] = {0.f, 0.f, 0.f, 0.f, 0.f};
    const int beg = g_off[node];
    const int end = g_off[node + 1];

    for (int p = beg; p < end; p += WB) {
        const int nb = min(WB, end - p);
        __syncthreads();
#pragma unroll
        for (int r = 0; r < 2; r++) {
            int v = tid + r * 320;
            int j = v / 80, idx = v - j * 80;
            if (j < nb) {
                int e = g_order[p + j];
                ((float4*)ys)[j * 80 + idx] =
                    ((const float4*)(g_y + (size_t)e * 320))[idx];
            }
        }
        if (tid < 200) {
            int j = tid / 25, m = tid - j * 25;
            if (j < nb) {
                int e = g_order[p + j];
                const float* wp = wig + (size_t)e * 625 + m * 25;
                float* dp = sw + j * 256 + m * 8;
                *(float4*)dp = make_float4(wp[0], wp[1], wp[2], wp[3]);
                dp[4] = wp[4];
            }
        }
        __syncthreads();
        for (int j = 0; j < nb; j++) {
            const float* yy = ys + j * 320;
            float y0 = yy[c], y1 = yy[64 + c], y2 = yy[128 + c],
                  y3 = yy[192 + c], y4 = yy[256 + c];
            const float* wj = sw + j * 256 + mg * 40;
#pragma unroll
            for (int jm = 0; jm < 5; jm++) {
                float4 wv = *(const float4*)(wj + jm * 8);
                float w4 = (wj + jm * 8)[4];
                acc[jm] += wv.x * y0 + wv.y * y1 + wv.z * y2 + wv.w * y3 + w4 * y4;
            }
        }
    }
    float* op = out + (size_t)node * 1600;
#pragma unroll
    for (int jm = 0; jm < 5; jm++)
        op[(mg * 5 + jm) * 64 + c] = acc[jm];
}

// ============================================================================
extern "C" void kernel_launch(void* const* d_in, const int* in_sizes, int n_in,
                              void* d_out, int out_size)
{
    const int*   an   = (const int*)  d_in[0];
    const float* dist = (const float*)d_in[1];
    const int*   ei   = (const int*)  d_in[2];
    const float* env  = (const float*)d_in[3];
    const float* semb = (const float*)d_in[4];
    const float* temb = (const float*)d_in[5];
    const float* w0   = (const float*)d_in[6];
    const float* b0   = (const float*)d_in[7];
    const float* g0   = (const float*)d_in[8];
    const float* be0  = (const float*)d_in[9];
    const float* w1   = (const float*)d_in[10];
    const float* b1   = (const float*)d_in[11];
    const float* g1   = (const float*)d_in[12];
    const float* be1  = (const float*)d_in[13];
    const float* w2   = (const float*)d_in[14];
    const float* b2   = (const float*)d_in[15];
    const float* wig  = (const float*)d_in[16];
    float* out = (float*)d_out;

    // launch #4 gets profiled by the harness's ncu capture -> k_mlp012 there
    k_prep     <<<72, 256>>>(w0, w1, w2);
    k_pemb     <<<180, 128>>>(semb, temb, w0);
    k_zero_hist<<<(NNODES + 255) / 256, 256>>>();
    k_mlp012   <<<E_EDGES / 64, 256>>>(an, dist, ei, b0, g0, be0, b1, g1, be1, b2, env);
    k_hist     <<<E_EDGES / 256, 256>>>(ei);
    k_scan     <<<1, 1024>>>();
    k_scatter  <<<E_EDGES / 256, 256>>>(ei);
    k_wigner   <<<NNODES, 320>>>(wig, out);
}